// round 6
// baseline (speedup 1.0000x reference)
#include <cuda_runtime.h>
#include <cuda_bf16.h>
#include <cstdint>
#include <cstddef>

// ---------------------------------------------------------------------------
// Problem constants
// ---------------------------------------------------------------------------
static constexpr int BATCH   = 2;
static constexpr int SEQ     = 2048;
static constexpr int HID     = 4096;
static constexpr int NHEADS  = 32;
static constexpr int HDIM    = 128;
static constexpr int QRANK   = 1536;
static constexpr int KVRANK  = 512;
static constexpr int TOKENS  = BATCH * SEQ;            // 4096
static constexpr int MODEL   = NHEADS * HDIM;          // 4096
static constexpr float SM_SCALE = 0.08838834764831845f; // 1/sqrt(128)

// ---------------------------------------------------------------------------
// Scratch (static device allocations; no cudaMalloc anywhere)
// ---------------------------------------------------------------------------
__device__ float g_qc[(size_t)TOKENS * QRANK];
__device__ float g_q [(size_t)TOKENS * MODEL];
__device__ float g_k [(size_t)TOKENS * MODEL];
__device__ float g_v [(size_t)TOKENS * MODEL];
__device__ float g_ao[(size_t)TOKENS * MODEL];

// ---------------------------------------------------------------------------
// Helpers
// ---------------------------------------------------------------------------
__device__ __forceinline__ uint32_t f2tf32(float x) {
    uint32_t r;
    asm("cvt.rna.tf32.f32 %0, %1;" : "=r"(r) : "f"(x));
    return r;
}

__device__ __forceinline__ void mma_tf32(float c[4], const uint32_t a[4],
                                         const uint32_t b[2]) {
    asm volatile(
        "mma.sync.aligned.m16n8k8.row.col.f32.tf32.tf32.f32 "
        "{%0,%1,%2,%3}, {%4,%5,%6,%7}, {%8,%9}, {%0,%1,%2,%3};"
        : "+f"(c[0]), "+f"(c[1]), "+f"(c[2]), "+f"(c[3])
        : "r"(a[0]), "r"(a[1]), "r"(a[2]), "r"(a[3]), "r"(b[0]), "r"(b[1]));
}

// ---------------------------------------------------------------------------
// mma.sync tf32 GEMM:  C[M,N] = A[M,K] @ B[K,N]  (both row-major)
// (verified round-3 version, unchanged)
// ---------------------------------------------------------------------------
static constexpr int A_LD = 36;
static constexpr int B_LD = 136;
static constexpr int A_FLOATS = 128 * A_LD;
static constexpr int B_FLOATS = 32 * B_LD;
static constexpr int STAGE_FLOATS = A_FLOATS + B_FLOATS;
static constexpr int GEMM_SMEM_BYTES = 2 * STAGE_FLOATS * 4;

__global__ __launch_bounds__(256) void gemm_mma(
    const float* __restrict__ A, const float* __restrict__ B,
    float* __restrict__ C, int M, int N, int K)
{
    extern __shared__ uint32_t smu[];
    const int tid  = threadIdx.x;
    const int wid  = tid >> 5;
    const int lane = tid & 31;
    const int warpM = wid >> 2;
    const int warpN = wid & 3;
    const int m0 = blockIdx.y * 128;
    const int n0 = blockIdx.x * 128;
    const int r  = lane >> 2;
    const int cq = lane & 3;

    float acc[4][4][4];
#pragma unroll
    for (int mi = 0; mi < 4; mi++)
#pragma unroll
        for (int nj = 0; nj < 4; nj++)
#pragma unroll
            for (int t = 0; t < 4; t++) acc[mi][nj][t] = 0.f;

    const int ac4 = (tid & 7) << 2;
    const int bn4 = (tid & 31) << 2;

    float4 av[4], bv[4];
    const int KT = K >> 5;

    {
        const int k0 = 0;
#pragma unroll
        for (int i = 0; i < 4; i++) {
            av[i] = *(const float4*)(A + (size_t)(m0 + (tid >> 3) + i * 32) * K + k0 + ac4);
            bv[i] = *(const float4*)(B + (size_t)(k0 + (tid >> 5) + i * 8) * N + n0 + bn4);
        }
    }
    {
        uint32_t* as = smu;
        uint32_t* bs = smu + A_FLOATS;
#pragma unroll
        for (int i = 0; i < 4; i++) {
            uint4 t = { f2tf32(av[i].x), f2tf32(av[i].y), f2tf32(av[i].z), f2tf32(av[i].w) };
            *(uint4*)&as[((tid >> 3) + i * 32) * A_LD + ac4] = t;
            uint4 u = { f2tf32(bv[i].x), f2tf32(bv[i].y), f2tf32(bv[i].z), f2tf32(bv[i].w) };
            *(uint4*)&bs[((tid >> 5) + i * 8) * B_LD + bn4] = u;
        }
    }
    __syncthreads();

    for (int it = 0; it < KT; ++it) {
        const int s = it & 1;
        if (it + 1 < KT) {
            const int k0 = (it + 1) << 5;
#pragma unroll
            for (int i = 0; i < 4; i++) {
                av[i] = *(const float4*)(A + (size_t)(m0 + (tid >> 3) + i * 32) * K + k0 + ac4);
                bv[i] = *(const float4*)(B + (size_t)(k0 + (tid >> 5) + i * 8) * N + n0 + bn4);
            }
        }

        const uint32_t* as = smu + s * STAGE_FLOATS;
        const uint32_t* bs = smu + s * STAGE_FLOATS + A_FLOATS;
#pragma unroll
        for (int ks = 0; ks < 4; ++ks) {
            uint32_t af[4][4];
#pragma unroll
            for (int mi = 0; mi < 4; mi++) {
                int rb = (warpM * 64 + mi * 16 + r) * A_LD + ks * 8 + cq;
                af[mi][0] = as[rb];
                af[mi][1] = as[rb + 8 * A_LD];
                af[mi][2] = as[rb + 4];
                af[mi][3] = as[rb + 8 * A_LD + 4];
            }
            uint32_t bf[4][2];
#pragma unroll
            for (int nj = 0; nj < 4; nj++) {
                int bb = (ks * 8 + cq) * B_LD + warpN * 32 + nj * 8 + r;
                bf[nj][0] = bs[bb];
                bf[nj][1] = bs[bb + 4 * B_LD];
            }
#pragma unroll
            for (int mi = 0; mi < 4; mi++)
#pragma unroll
                for (int nj = 0; nj < 4; nj++)
                    mma_tf32(acc[mi][nj], af[mi], bf[nj]);
        }

        if (it + 1 < KT) {
            uint32_t* asn = smu + (s ^ 1) * STAGE_FLOATS;
            uint32_t* bsn = smu + (s ^ 1) * STAGE_FLOATS + A_FLOATS;
#pragma unroll
            for (int i = 0; i < 4; i++) {
                uint4 t = { f2tf32(av[i].x), f2tf32(av[i].y), f2tf32(av[i].z), f2tf32(av[i].w) };
                *(uint4*)&asn[((tid >> 3) + i * 32) * A_LD + ac4] = t;
                uint4 u = { f2tf32(bv[i].x), f2tf32(bv[i].y), f2tf32(bv[i].z), f2tf32(bv[i].w) };
                *(uint4*)&bsn[((tid >> 5) + i * 8) * B_LD + bn4] = u;
            }
            __syncthreads();
        }
    }

#pragma unroll
    for (int mi = 0; mi < 4; mi++) {
        const int row0 = m0 + warpM * 64 + mi * 16 + r;
#pragma unroll
        for (int nj = 0; nj < 4; nj++) {
            const int col = n0 + warpN * 32 + nj * 8 + 2 * cq;
            *(float2*)&C[(size_t)row0 * N + col] =
                make_float2(acc[mi][nj][0], acc[mi][nj][1]);
            *(float2*)&C[(size_t)(row0 + 8) * N + col] =
                make_float2(acc[mi][nj][2], acc[mi][nj][3]);
        }
    }
}

// ---------------------------------------------------------------------------
// Tensor-core flash attention (causal), tf32 mma + fp32 online softmax.
// v4: register-pressure fix. Q fragments live in a fragment-ordered smem
// region (one LDS.128 per k-step) instead of 64 registers; no prefetch
// registers. Long-lived state = O accumulators (64 regs) + softmax (4).
// CTA: 128 queries; 8 warps, warp w owns q rows [w*16, w*16+16).
// ---------------------------------------------------------------------------
static constexpr int FQ = 128;
static constexpr int FK = 64;
static constexpr int KV_LD = 132;                 // u32; %32==4 -> conflict-free frags
static constexpr int P_LD  = 68;                  // u32; %32==4
static constexpr int KVW = 128 * KV_LD;           // K rows 0-63, V rows 64-127
static constexpr int PW  = 128 * P_LD;
static constexpr int QFW = 128 * 128;             // fragment-ordered Q (64 KB)
static constexpr int FLASH_SMEM_BYTES = (KVW + PW + QFW) * 4;   // 167,936

__global__ __launch_bounds__(256) void flash_tc(
    const float* __restrict__ Q, const float* __restrict__ K,
    const float* __restrict__ V, float* __restrict__ O)
{
    extern __shared__ uint32_t fsm[];
    uint32_t* kvs = fsm;
    uint32_t* Ps  = fsm + KVW;
    uint32_t* Qf  = fsm + KVW + PW;

    const int tid  = threadIdx.x;
    const int wq   = tid >> 5;
    const int lane = tid & 31;
    const int r    = lane >> 2;
    const int cq   = lane & 3;
    const int mtile = blockIdx.x;
    const int head  = blockIdx.y;
    const int b     = blockIdx.z;
    const int m0    = mtile * FQ;
    const size_t base = ((size_t)b * SEQ) * MODEL + (size_t)head * HDIM;

    // ---- stage Q (pre-scaled tf32) linearly through kvs ----
    for (int it = tid; it < 128 * 32; it += 256) {
        int row = it >> 5, c4 = (it & 31) << 2;
        float4 v = *(const float4*)&Q[base + (size_t)(m0 + row) * MODEL + c4];
        uint4 t = { f2tf32(v.x * SM_SCALE), f2tf32(v.y * SM_SCALE),
                    f2tf32(v.z * SM_SCALE), f2tf32(v.w * SM_SCALE) };
        *(uint4*)&kvs[row * KV_LD + c4] = t;
    }
    __syncthreads();

    // ---- repack Q into fragment-ordered smem: Qf[((wq*16+ks)*32+lane)*4] ----
#pragma unroll
    for (int ks = 0; ks < 16; ks++) {
        int rb = (wq * 16 + r) * KV_LD + ks * 8 + cq;
        uint4 qv = { kvs[rb], kvs[rb + 8 * KV_LD],
                     kvs[rb + 4], kvs[rb + 8 * KV_LD + 4] };
        *(uint4*)&Qf[(((wq * 16 + ks) * 32) + lane) * 4] = qv;
    }
    __syncthreads();   // everyone done with staged Q before KV overwrites kvs

    float of[16][4];
#pragma unroll
    for (int nj = 0; nj < 16; nj++)
#pragma unroll
        for (int t = 0; t < 4; t++) of[nj][t] = 0.f;

    float mrow0 = -1e30f, mrow1 = -1e30f, lrow0 = 0.f, lrow1 = 0.f;
    const int row0 = m0 + wq * 16 + r;
    const int row1 = row0 + 8;

    const int NT = 2 * (mtile + 1);
    for (int t = 0; t < NT; t++) {
        const int n0 = t * FK;

        // ---- load KV tile (single buffer) ----
        for (int it = tid; it < 64 * 32; it += 256) {
            int row = it >> 5, c4 = (it & 31) << 2;
            size_t g = base + (size_t)(n0 + row) * MODEL + c4;
            float4 k4 = *(const float4*)&K[g];
            float4 v4 = *(const float4*)&V[g];
            uint4 tk = { f2tf32(k4.x), f2tf32(k4.y), f2tf32(k4.z), f2tf32(k4.w) };
            uint4 tv = { f2tf32(v4.x), f2tf32(v4.y), f2tf32(v4.z), f2tf32(v4.w) };
            *(uint4*)&kvs[row * KV_LD + c4]        = tk;
            *(uint4*)&kvs[(64 + row) * KV_LD + c4] = tv;
        }
        __syncthreads();

        // ---- S = Q K^T : Q frags from Qf (1 LDS.128 per ks) ----
        float sc[8][4];
#pragma unroll
        for (int nj = 0; nj < 8; nj++)
#pragma unroll
            for (int e = 0; e < 4; e++) sc[nj][e] = 0.f;

#pragma unroll
        for (int ks = 0; ks < 16; ks++) {
            uint4 qa4 = *(const uint4*)&Qf[(((wq * 16 + ks) * 32) + lane) * 4];
            uint32_t qa[4] = { qa4.x, qa4.y, qa4.z, qa4.w };
#pragma unroll
            for (int nj = 0; nj < 8; nj++) {
                uint32_t bb[2];
                int ib = (nj * 8 + r) * KV_LD + ks * 8 + cq;
                bb[0] = kvs[ib];
                bb[1] = kvs[ib + 4];
                mma_tf32(sc[nj], qa, bb);
            }
        }

        // ---- causal mask (diagonal tiles only) ----
        if (n0 + FK - 1 > m0) {
#pragma unroll
            for (int nj = 0; nj < 8; nj++) {
                int kk = n0 + nj * 8 + 2 * cq;
                if (kk     > row0) sc[nj][0] = -1e30f;
                if (kk + 1 > row0) sc[nj][1] = -1e30f;
                if (kk     > row1) sc[nj][2] = -1e30f;
                if (kk + 1 > row1) sc[nj][3] = -1e30f;
            }
        }

        // ---- online softmax (warp-local rows; quad shuffles) ----
        float tmax0 = -1e30f, tmax1 = -1e30f;
#pragma unroll
        for (int nj = 0; nj < 8; nj++) {
            tmax0 = fmaxf(tmax0, fmaxf(sc[nj][0], sc[nj][1]));
            tmax1 = fmaxf(tmax1, fmaxf(sc[nj][2], sc[nj][3]));
        }
        tmax0 = fmaxf(tmax0, __shfl_xor_sync(0xffffffffu, tmax0, 1));
        tmax0 = fmaxf(tmax0, __shfl_xor_sync(0xffffffffu, tmax0, 2));
        tmax1 = fmaxf(tmax1, __shfl_xor_sync(0xffffffffu, tmax1, 1));
        tmax1 = fmaxf(tmax1, __shfl_xor_sync(0xffffffffu, tmax1, 2));

        float nm0 = fmaxf(mrow0, tmax0);
        float nm1 = fmaxf(mrow1, tmax1);
        float c0 = __expf(mrow0 - nm0);
        float c1 = __expf(mrow1 - nm1);
        float ts0 = 0.f, ts1 = 0.f;
#pragma unroll
        for (int nj = 0; nj < 8; nj++) {
            float p0 = __expf(sc[nj][0] - nm0);
            float p1 = __expf(sc[nj][1] - nm0);
            float p2 = __expf(sc[nj][2] - nm1);
            float p3 = __expf(sc[nj][3] - nm1);
            ts0 += p0 + p1;
            ts1 += p2 + p3;
            uint2 u0 = { f2tf32(p0), f2tf32(p1) };
            uint2 u1 = { f2tf32(p2), f2tf32(p3) };
            *(uint2*)&Ps[(wq * 16 + r) * P_LD + nj * 8 + 2 * cq]     = u0;
            *(uint2*)&Ps[(wq * 16 + r + 8) * P_LD + nj * 8 + 2 * cq] = u1;
        }
        ts0 += __shfl_xor_sync(0xffffffffu, ts0, 1);
        ts0 += __shfl_xor_sync(0xffffffffu, ts0, 2);
        ts1 += __shfl_xor_sync(0xffffffffu, ts1, 1);
        ts1 += __shfl_xor_sync(0xffffffffu, ts1, 2);

        mrow0 = nm0; mrow1 = nm1;
        lrow0 = lrow0 * c0 + ts0;
        lrow1 = lrow1 * c1 + ts1;
#pragma unroll
        for (int nj = 0; nj < 16; nj++) {
            of[nj][0] *= c0; of[nj][1] *= c0;
            of[nj][2] *= c1; of[nj][3] *= c1;
        }
        __syncwarp();   // P visible within warp

        // ---- O += P V ----
#pragma unroll
        for (int ks = 0; ks < 8; ks++) {
            uint32_t ap[4];
            int rb = (wq * 16 + r) * P_LD + ks * 8 + cq;
            ap[0] = Ps[rb];
            ap[1] = Ps[rb + 8 * P_LD];
            ap[2] = Ps[rb + 4];
            ap[3] = Ps[rb + 8 * P_LD + 4];
#pragma unroll
            for (int nj = 0; nj < 16; nj++) {
                uint32_t bb[2];
                int ib = (64 + ks * 8 + cq) * KV_LD + nj * 8 + r;
                bb[0] = kvs[ib];
                bb[1] = kvs[ib + 4 * KV_LD];
                mma_tf32(of[nj], ap, bb);
            }
        }
        __syncthreads();   // all warps done with kvs before next tile overwrites
    }

    // ---- epilogue ----
    const float inv0 = 1.f / lrow0;
    const float inv1 = 1.f / lrow1;
#pragma unroll
    for (int nj = 0; nj < 16; nj++) {
        int col = nj * 8 + 2 * cq;
        *(float2*)&O[base + (size_t)row0 * MODEL + col] =
            make_float2(of[nj][0] * inv0, of[nj][1] * inv0);
        *(float2*)&O[base + (size_t)row1 * MODEL + col] =
            make_float2(of[nj][2] * inv1, of[nj][3] * inv1);
    }
}

// ---------------------------------------------------------------------------
// Launch
// ---------------------------------------------------------------------------
static inline void run_gemm(const float* A, const float* B, float* C,
                            int M, int N, int K, cudaStream_t stream)
{
    dim3 grid(N / 128, M / 128);
    gemm_mma<<<grid, 256, GEMM_SMEM_BYTES, stream>>>(A, B, C, M, N, K);
}

extern "C" void kernel_launch(void* const* d_in, const int* in_sizes, int n_in,
                              void* d_out, int out_size)
{
    (void)in_sizes; (void)n_in; (void)out_size;
    const float* X     = (const float*)d_in[0];
    const float* w_qa  = (const float*)d_in[1];
    const float* w_qb  = (const float*)d_in[2];
    const float* w_kva = (const float*)d_in[3];
    const float* w_kb  = (const float*)d_in[4];
    const float* w_vb  = (const float*)d_in[5];
    const float* w_o   = (const float*)d_in[6];

    float* attn_out = (float*)d_out;
    float* ckv      = (float*)d_out + (size_t)TOKENS * HID;

    float *qc, *q, *k, *v, *ao;
    cudaGetSymbolAddress((void**)&qc, g_qc);
    cudaGetSymbolAddress((void**)&q,  g_q);
    cudaGetSymbolAddress((void**)&k,  g_k);
    cudaGetSymbolAddress((void**)&v,  g_v);
    cudaGetSymbolAddress((void**)&ao, g_ao);

    cudaFuncSetAttribute(gemm_mma,
                         cudaFuncAttributeMaxDynamicSharedMemorySize,
                         GEMM_SMEM_BYTES);
    cudaFuncSetAttribute(flash_tc,
                         cudaFuncAttributeMaxDynamicSharedMemorySize,
                         FLASH_SMEM_BYTES);

    cudaStream_t stream = 0;

    // projections (tensor-core tf32)
    run_gemm(X,   w_qa,  qc,  TOKENS, QRANK,  HID,    stream);
    run_gemm(qc,  w_qb,  q,   TOKENS, MODEL,  QRANK,  stream);
    run_gemm(X,   w_kva, ckv, TOKENS, KVRANK, HID,    stream);
    run_gemm(ckv, w_kb,  k,   TOKENS, MODEL,  KVRANK, stream);
    run_gemm(ckv, w_vb,  v,   TOKENS, MODEL,  KVRANK, stream);

    // causal attention (tensor-core tf32, register-pressure-fixed)
    dim3 fgrid(SEQ / FQ, NHEADS, BATCH);
    flash_tc<<<fgrid, 256, FLASH_SMEM_BYTES, stream>>>(q, k, v, ao);

    // output projection
    run_gemm(ao, w_o, attn_out, TOKENS, HID, MODEL, stream);
}

// round 7
// speedup vs baseline: 1.0604x; 1.0604x over previous
#include <cuda_runtime.h>
#include <cuda_bf16.h>
#include <cstdint>
#include <cstddef>

// ---------------------------------------------------------------------------
// Problem constants
// ---------------------------------------------------------------------------
static constexpr int BATCH   = 2;
static constexpr int SEQ     = 2048;
static constexpr int HID     = 4096;
static constexpr int NHEADS  = 32;
static constexpr int HDIM    = 128;
static constexpr int QRANK   = 1536;
static constexpr int KVRANK  = 512;
static constexpr int TOKENS  = BATCH * SEQ;            // 4096
static constexpr int MODEL   = NHEADS * HDIM;          // 4096
static constexpr float SM_SCALE = 0.08838834764831845f; // 1/sqrt(128)

// ---------------------------------------------------------------------------
// Scratch (static device allocations; no cudaMalloc anywhere)
// ---------------------------------------------------------------------------
__device__ float g_qc[(size_t)TOKENS * QRANK];
__device__ float g_q [(size_t)TOKENS * MODEL];
__device__ float g_k [(size_t)TOKENS * MODEL];
__device__ float g_v [(size_t)TOKENS * MODEL];
__device__ float g_ao[(size_t)TOKENS * MODEL];

// ---------------------------------------------------------------------------
// Helpers
// ---------------------------------------------------------------------------
__device__ __forceinline__ uint32_t f2tf32(float x) {
    uint32_t r;
    asm("cvt.rna.tf32.f32 %0, %1;" : "=r"(r) : "f"(x));
    return r;
}

__device__ __forceinline__ void mma_tf32(float c[4], const uint32_t a[4],
                                         const uint32_t b[2]) {
    asm volatile(
        "mma.sync.aligned.m16n8k8.row.col.f32.tf32.tf32.f32 "
        "{%0,%1,%2,%3}, {%4,%5,%6,%7}, {%8,%9}, {%0,%1,%2,%3};"
        : "+f"(c[0]), "+f"(c[1]), "+f"(c[2]), "+f"(c[3])
        : "r"(a[0]), "r"(a[1]), "r"(a[2]), "r"(a[3]), "r"(b[0]), "r"(b[1]));
}

// ---------------------------------------------------------------------------
// mma.sync tf32 GEMM:  C[M,N] = A[M,K] @ B[K,N]  (both row-major)
// (verified round-3 version, unchanged)
// ---------------------------------------------------------------------------
static constexpr int A_LD = 36;
static constexpr int B_LD = 136;
static constexpr int A_FLOATS = 128 * A_LD;
static constexpr int B_FLOATS = 32 * B_LD;
static constexpr int STAGE_FLOATS = A_FLOATS + B_FLOATS;
static constexpr int GEMM_SMEM_BYTES = 2 * STAGE_FLOATS * 4;

__global__ __launch_bounds__(256) void gemm_mma(
    const float* __restrict__ A, const float* __restrict__ B,
    float* __restrict__ C, int M, int N, int K)
{
    extern __shared__ uint32_t smu[];
    const int tid  = threadIdx.x;
    const int wid  = tid >> 5;
    const int lane = tid & 31;
    const int warpM = wid >> 2;
    const int warpN = wid & 3;
    const int m0 = blockIdx.y * 128;
    const int n0 = blockIdx.x * 128;
    const int r  = lane >> 2;
    const int cq = lane & 3;

    float acc[4][4][4];
#pragma unroll
    for (int mi = 0; mi < 4; mi++)
#pragma unroll
        for (int nj = 0; nj < 4; nj++)
#pragma unroll
            for (int t = 0; t < 4; t++) acc[mi][nj][t] = 0.f;

    const int ac4 = (tid & 7) << 2;
    const int bn4 = (tid & 31) << 2;

    float4 av[4], bv[4];
    const int KT = K >> 5;

    {
        const int k0 = 0;
#pragma unroll
        for (int i = 0; i < 4; i++) {
            av[i] = *(const float4*)(A + (size_t)(m0 + (tid >> 3) + i * 32) * K + k0 + ac4);
            bv[i] = *(const float4*)(B + (size_t)(k0 + (tid >> 5) + i * 8) * N + n0 + bn4);
        }
    }
    {
        uint32_t* as = smu;
        uint32_t* bs = smu + A_FLOATS;
#pragma unroll
        for (int i = 0; i < 4; i++) {
            uint4 t = { f2tf32(av[i].x), f2tf32(av[i].y), f2tf32(av[i].z), f2tf32(av[i].w) };
            *(uint4*)&as[((tid >> 3) + i * 32) * A_LD + ac4] = t;
            uint4 u = { f2tf32(bv[i].x), f2tf32(bv[i].y), f2tf32(bv[i].z), f2tf32(bv[i].w) };
            *(uint4*)&bs[((tid >> 5) + i * 8) * B_LD + bn4] = u;
        }
    }
    __syncthreads();

    for (int it = 0; it < KT; ++it) {
        const int s = it & 1;
        if (it + 1 < KT) {
            const int k0 = (it + 1) << 5;
#pragma unroll
            for (int i = 0; i < 4; i++) {
                av[i] = *(const float4*)(A + (size_t)(m0 + (tid >> 3) + i * 32) * K + k0 + ac4);
                bv[i] = *(const float4*)(B + (size_t)(k0 + (tid >> 5) + i * 8) * N + n0 + bn4);
            }
        }

        const uint32_t* as = smu + s * STAGE_FLOATS;
        const uint32_t* bs = smu + s * STAGE_FLOATS + A_FLOATS;
#pragma unroll
        for (int ks = 0; ks < 4; ++ks) {
            uint32_t af[4][4];
#pragma unroll
            for (int mi = 0; mi < 4; mi++) {
                int rb = (warpM * 64 + mi * 16 + r) * A_LD + ks * 8 + cq;
                af[mi][0] = as[rb];
                af[mi][1] = as[rb + 8 * A_LD];
                af[mi][2] = as[rb + 4];
                af[mi][3] = as[rb + 8 * A_LD + 4];
            }
            uint32_t bf[4][2];
#pragma unroll
            for (int nj = 0; nj < 4; nj++) {
                int bb = (ks * 8 + cq) * B_LD + warpN * 32 + nj * 8 + r;
                bf[nj][0] = bs[bb];
                bf[nj][1] = bs[bb + 4 * B_LD];
            }
#pragma unroll
            for (int mi = 0; mi < 4; mi++)
#pragma unroll
                for (int nj = 0; nj < 4; nj++)
                    mma_tf32(acc[mi][nj], af[mi], bf[nj]);
        }

        if (it + 1 < KT) {
            uint32_t* asn = smu + (s ^ 1) * STAGE_FLOATS;
            uint32_t* bsn = smu + (s ^ 1) * STAGE_FLOATS + A_FLOATS;
#pragma unroll
            for (int i = 0; i < 4; i++) {
                uint4 t = { f2tf32(av[i].x), f2tf32(av[i].y), f2tf32(av[i].z), f2tf32(av[i].w) };
                *(uint4*)&asn[((tid >> 3) + i * 32) * A_LD + ac4] = t;
                uint4 u = { f2tf32(bv[i].x), f2tf32(bv[i].y), f2tf32(bv[i].z), f2tf32(bv[i].w) };
                *(uint4*)&bsn[((tid >> 5) + i * 8) * B_LD + bn4] = u;
            }
            __syncthreads();
        }
    }

#pragma unroll
    for (int mi = 0; mi < 4; mi++) {
        const int row0 = m0 + warpM * 64 + mi * 16 + r;
#pragma unroll
        for (int nj = 0; nj < 4; nj++) {
            const int col = n0 + warpN * 32 + nj * 8 + 2 * cq;
            *(float2*)&C[(size_t)row0 * N + col] =
                make_float2(acc[mi][nj][0], acc[mi][nj][1]);
            *(float2*)&C[(size_t)(row0 + 8) * N + col] =
                make_float2(acc[mi][nj][2], acc[mi][nj][3]);
        }
    }
}

// ---------------------------------------------------------------------------
// Tensor-core flash attention (causal), tf32 mma + fp32 online softmax.
// v5: gemm-style fragment batching — per k-step, ALL B fragments are loaded
// into register arrays before the MMA batch (the schedule that measures at
// model in gemm_mma). Separate V stride (136) makes PV B-fragment loads
// bank-conflict-free (8*cq+r bijective); K keeps 132 (4*r+cq bijective).
// CTA: 128 queries; 8 warps, warp w owns q rows [w*16, w*16+16).
// ---------------------------------------------------------------------------
static constexpr int FQ = 128;
static constexpr int FK = 64;
static constexpr int K_LD = 132;                  // u32; bank = 4r+cq (bijective)
static constexpr int V_LD = 136;                  // u32; bank = 8cq+r (bijective)
static constexpr int P_LD = 68;                   // u32
static constexpr int KW  = 64 * K_LD;             // 8448
static constexpr int VW  = 64 * V_LD;             // 8704
static constexpr int PW  = 128 * P_LD;            // 8704
static constexpr int QFW = 128 * 128;             // 16384 (fragment-ordered Q)
static constexpr int FLASH_SMEM_BYTES = (KW + VW + PW + QFW) * 4;   // 168,960

__global__ __launch_bounds__(256) void flash_tc(
    const float* __restrict__ Q, const float* __restrict__ K,
    const float* __restrict__ V, float* __restrict__ O)
{
    extern __shared__ uint32_t fsm[];
    uint32_t* Ks = fsm;
    uint32_t* Vs = fsm + KW;
    uint32_t* Ps = fsm + KW + VW;
    uint32_t* Qf = fsm + KW + VW + PW;

    const int tid  = threadIdx.x;
    const int wq   = tid >> 5;
    const int lane = tid & 31;
    const int r    = lane >> 2;
    const int cq   = lane & 3;
    const int mtile = blockIdx.x;
    const int head  = blockIdx.y;
    const int b     = blockIdx.z;
    const int m0    = mtile * FQ;
    const size_t base = ((size_t)b * SEQ) * MODEL + (size_t)head * HDIM;

    // ---- stage Q (pre-scaled tf32) linearly through the K/V/P region ----
    for (int it = tid; it < 128 * 32; it += 256) {
        int row = it >> 5, c4 = (it & 31) << 2;
        float4 v = *(const float4*)&Q[base + (size_t)(m0 + row) * MODEL + c4];
        uint4 t = { f2tf32(v.x * SM_SCALE), f2tf32(v.y * SM_SCALE),
                    f2tf32(v.z * SM_SCALE), f2tf32(v.w * SM_SCALE) };
        *(uint4*)&fsm[row * K_LD + c4] = t;
    }
    __syncthreads();

    // ---- repack Q into fragment-ordered smem ----
#pragma unroll
    for (int ks = 0; ks < 16; ks++) {
        int rb = (wq * 16 + r) * K_LD + ks * 8 + cq;
        uint4 qv = { fsm[rb], fsm[rb + 8 * K_LD],
                     fsm[rb + 4], fsm[rb + 8 * K_LD + 4] };
        *(uint4*)&Qf[(((wq * 16 + ks) * 32) + lane) * 4] = qv;
    }
    __syncthreads();   // Q staged area may now be overwritten by K/V tiles

    float of[16][4];
#pragma unroll
    for (int nj = 0; nj < 16; nj++)
#pragma unroll
        for (int t = 0; t < 4; t++) of[nj][t] = 0.f;

    float mrow0 = -1e30f, mrow1 = -1e30f, lrow0 = 0.f, lrow1 = 0.f;
    const int row0 = m0 + wq * 16 + r;
    const int row1 = row0 + 8;

    const int NT = 2 * (mtile + 1);
    for (int t = 0; t < NT; t++) {
        const int n0 = t * FK;

        // ---- load KV tile ----
        for (int it = tid; it < 64 * 32; it += 256) {
            int row = it >> 5, c4 = (it & 31) << 2;
            size_t g = base + (size_t)(n0 + row) * MODEL + c4;
            float4 k4 = *(const float4*)&K[g];
            float4 v4 = *(const float4*)&V[g];
            uint4 tk = { f2tf32(k4.x), f2tf32(k4.y), f2tf32(k4.z), f2tf32(k4.w) };
            uint4 tv = { f2tf32(v4.x), f2tf32(v4.y), f2tf32(v4.z), f2tf32(v4.w) };
            *(uint4*)&Ks[row * K_LD + c4] = tk;
            *(uint4*)&Vs[row * V_LD + c4] = tv;
        }
        __syncthreads();

        // ---- S = Q K^T : per ks, batch-load all fragments, then MMA batch ----
        float sc[8][4];
#pragma unroll
        for (int nj = 0; nj < 8; nj++)
#pragma unroll
            for (int e = 0; e < 4; e++) sc[nj][e] = 0.f;

#pragma unroll
        for (int ks = 0; ks < 16; ks++) {
            uint4 qa4 = *(const uint4*)&Qf[(((wq * 16 + ks) * 32) + lane) * 4];
            uint32_t qa[4] = { qa4.x, qa4.y, qa4.z, qa4.w };
            uint32_t bf[8][2];
#pragma unroll
            for (int nj = 0; nj < 8; nj++) {
                int ib = (nj * 8 + r) * K_LD + ks * 8 + cq;
                bf[nj][0] = Ks[ib];
                bf[nj][1] = Ks[ib + 4];
            }
#pragma unroll
            for (int nj = 0; nj < 8; nj++)
                mma_tf32(sc[nj], qa, bf[nj]);
        }

        // ---- causal mask (diagonal tiles only) ----
        if (n0 + FK - 1 > m0) {
#pragma unroll
            for (int nj = 0; nj < 8; nj++) {
                int kk = n0 + nj * 8 + 2 * cq;
                if (kk     > row0) sc[nj][0] = -1e30f;
                if (kk + 1 > row0) sc[nj][1] = -1e30f;
                if (kk     > row1) sc[nj][2] = -1e30f;
                if (kk + 1 > row1) sc[nj][3] = -1e30f;
            }
        }

        // ---- online softmax (warp-local rows; quad shuffles) ----
        float tmax0 = -1e30f, tmax1 = -1e30f;
#pragma unroll
        for (int nj = 0; nj < 8; nj++) {
            tmax0 = fmaxf(tmax0, fmaxf(sc[nj][0], sc[nj][1]));
            tmax1 = fmaxf(tmax1, fmaxf(sc[nj][2], sc[nj][3]));
        }
        tmax0 = fmaxf(tmax0, __shfl_xor_sync(0xffffffffu, tmax0, 1));
        tmax0 = fmaxf(tmax0, __shfl_xor_sync(0xffffffffu, tmax0, 2));
        tmax1 = fmaxf(tmax1, __shfl_xor_sync(0xffffffffu, tmax1, 1));
        tmax1 = fmaxf(tmax1, __shfl_xor_sync(0xffffffffu, tmax1, 2));

        float nm0 = fmaxf(mrow0, tmax0);
        float nm1 = fmaxf(mrow1, tmax1);
        float c0 = __expf(mrow0 - nm0);
        float c1 = __expf(mrow1 - nm1);
        float ts0 = 0.f, ts1 = 0.f;
#pragma unroll
        for (int nj = 0; nj < 8; nj++) {
            float p0 = __expf(sc[nj][0] - nm0);
            float p1 = __expf(sc[nj][1] - nm0);
            float p2 = __expf(sc[nj][2] - nm1);
            float p3 = __expf(sc[nj][3] - nm1);
            ts0 += p0 + p1;
            ts1 += p2 + p3;
            uint2 u0 = { f2tf32(p0), f2tf32(p1) };
            uint2 u1 = { f2tf32(p2), f2tf32(p3) };
            *(uint2*)&Ps[(wq * 16 + r) * P_LD + nj * 8 + 2 * cq]     = u0;
            *(uint2*)&Ps[(wq * 16 + r + 8) * P_LD + nj * 8 + 2 * cq] = u1;
        }
        ts0 += __shfl_xor_sync(0xffffffffu, ts0, 1);
        ts0 += __shfl_xor_sync(0xffffffffu, ts0, 2);
        ts1 += __shfl_xor_sync(0xffffffffu, ts1, 1);
        ts1 += __shfl_xor_sync(0xffffffffu, ts1, 2);

        mrow0 = nm0; mrow1 = nm1;
        lrow0 = lrow0 * c0 + ts0;
        lrow1 = lrow1 * c1 + ts1;
#pragma unroll
        for (int nj = 0; nj < 16; nj++) {
            of[nj][0] *= c0; of[nj][1] *= c0;
            of[nj][2] *= c1; of[nj][3] *= c1;
        }
        __syncwarp();   // P visible within warp

        // ---- O += P V : per ks, batch-load all fragments, then MMA batch ----
#pragma unroll
        for (int ks = 0; ks < 8; ks++) {
            uint32_t ap[4];
            int rb = (wq * 16 + r) * P_LD + ks * 8 + cq;
            ap[0] = Ps[rb];
            ap[1] = Ps[rb + 8 * P_LD];
            ap[2] = Ps[rb + 4];
            ap[3] = Ps[rb + 8 * P_LD + 4];
            uint32_t bf[16][2];
#pragma unroll
            for (int nj = 0; nj < 16; nj++) {
                int ib = (ks * 8 + cq) * V_LD + nj * 8 + r;
                bf[nj][0] = Vs[ib];
                bf[nj][1] = Vs[ib + 4 * V_LD];
            }
#pragma unroll
            for (int nj = 0; nj < 16; nj++)
                mma_tf32(of[nj], ap, bf[nj]);
        }
        __syncthreads();   // all warps done with Ks/Vs before next tile
    }

    // ---- epilogue ----
    const float inv0 = 1.f / lrow0;
    const float inv1 = 1.f / lrow1;
#pragma unroll
    for (int nj = 0; nj < 16; nj++) {
        int col = nj * 8 + 2 * cq;
        *(float2*)&O[base + (size_t)row0 * MODEL + col] =
            make_float2(of[nj][0] * inv0, of[nj][1] * inv0);
        *(float2*)&O[base + (size_t)row1 * MODEL + col] =
            make_float2(of[nj][2] * inv1, of[nj][3] * inv1);
    }
}

// ---------------------------------------------------------------------------
// Launch
// ---------------------------------------------------------------------------
static inline void run_gemm(const float* A, const float* B, float* C,
                            int M, int N, int K, cudaStream_t stream)
{
    dim3 grid(N / 128, M / 128);
    gemm_mma<<<grid, 256, GEMM_SMEM_BYTES, stream>>>(A, B, C, M, N, K);
}

extern "C" void kernel_launch(void* const* d_in, const int* in_sizes, int n_in,
                              void* d_out, int out_size)
{
    (void)in_sizes; (void)n_in; (void)out_size;
    const float* X     = (const float*)d_in[0];
    const float* w_qa  = (const float*)d_in[1];
    const float* w_qb  = (const float*)d_in[2];
    const float* w_kva = (const float*)d_in[3];
    const float* w_kb  = (const float*)d_in[4];
    const float* w_vb  = (const float*)d_in[5];
    const float* w_o   = (const float*)d_in[6];

    float* attn_out = (float*)d_out;
    float* ckv      = (float*)d_out + (size_t)TOKENS * HID;

    float *qc, *q, *k, *v, *ao;
    cudaGetSymbolAddress((void**)&qc, g_qc);
    cudaGetSymbolAddress((void**)&q,  g_q);
    cudaGetSymbolAddress((void**)&k,  g_k);
    cudaGetSymbolAddress((void**)&v,  g_v);
    cudaGetSymbolAddress((void**)&ao, g_ao);

    cudaFuncSetAttribute(gemm_mma,
                         cudaFuncAttributeMaxDynamicSharedMemorySize,
                         GEMM_SMEM_BYTES);
    cudaFuncSetAttribute(flash_tc,
                         cudaFuncAttributeMaxDynamicSharedMemorySize,
                         FLASH_SMEM_BYTES);

    cudaStream_t stream = 0;

    // projections (tensor-core tf32)
    run_gemm(X,   w_qa,  qc,  TOKENS, QRANK,  HID,    stream);
    run_gemm(qc,  w_qb,  q,   TOKENS, MODEL,  QRANK,  stream);
    run_gemm(X,   w_kva, ckv, TOKENS, KVRANK, HID,    stream);
    run_gemm(ckv, w_kb,  k,   TOKENS, MODEL,  KVRANK, stream);
    run_gemm(ckv, w_vb,  v,   TOKENS, MODEL,  KVRANK, stream);

    // causal attention (tensor-core tf32, batched fragment scheduling)
    dim3 fgrid(SEQ / FQ, NHEADS, BATCH);
    flash_tc<<<fgrid, 256, FLASH_SMEM_BYTES, stream>>>(q, k, v, ao);

    // output projection
    run_gemm(ao, w_o, attn_out, TOKENS, HID, MODEL, stream);
}

// round 8
// speedup vs baseline: 1.2212x; 1.1516x over previous
#include <cuda_runtime.h>
#include <cuda_bf16.h>
#include <cstdint>
#include <cstddef>

// ---------------------------------------------------------------------------
// Problem constants
// ---------------------------------------------------------------------------
static constexpr int BATCH   = 2;
static constexpr int SEQ     = 2048;
static constexpr int HID     = 4096;
static constexpr int NHEADS  = 32;
static constexpr int HDIM    = 128;
static constexpr int QRANK   = 1536;
static constexpr int KVRANK  = 512;
static constexpr int TOKENS  = BATCH * SEQ;            // 4096
static constexpr int MODEL   = NHEADS * HDIM;          // 4096
static constexpr float SM_SCALE = 0.08838834764831845f; // 1/sqrt(128)

// ---------------------------------------------------------------------------
// Scratch (static device allocations; no cudaMalloc anywhere)
// ---------------------------------------------------------------------------
__device__ float g_qc[(size_t)TOKENS * QRANK];
__device__ float g_q [(size_t)TOKENS * MODEL];
__device__ float g_k [(size_t)TOKENS * MODEL];
__device__ float g_v [(size_t)TOKENS * MODEL];
__device__ float g_ao[(size_t)TOKENS * MODEL];

// ---------------------------------------------------------------------------
// Helpers
// ---------------------------------------------------------------------------
__device__ __forceinline__ uint32_t f2tf32(float x) {
    uint32_t r;
    asm("cvt.rna.tf32.f32 %0, %1;" : "=r"(r) : "f"(x));
    return r;
}
__device__ __forceinline__ uint32_t u2tf32(uint32_t bits) {
    uint32_t r;
    asm("cvt.rna.tf32.f32 %0, %1;" : "=r"(r) : "f"(__uint_as_float(bits)));
    return r;
}
__device__ __forceinline__ uint32_t smem_u32(const void* p) {
    uint32_t a;
    asm("{ .reg .u64 t; cvta.to.shared.u64 t, %1; cvt.u32.u64 %0, t; }"
        : "=r"(a) : "l"(p));
    return a;
}
__device__ __forceinline__ void cp_async16(uint32_t s, const void* g) {
    asm volatile("cp.async.cg.shared.global [%0], [%1], 16;" :: "r"(s), "l"(g));
}
#define CP_COMMIT() asm volatile("cp.async.commit_group;" ::: "memory")
#define CP_WAIT1()  asm volatile("cp.async.wait_group 1;" ::: "memory")

__device__ __forceinline__ void mma_tf32(float c[4], const uint32_t a[4],
                                         const uint32_t b[2]) {
    asm volatile(
        "mma.sync.aligned.m16n8k8.row.col.f32.tf32.tf32.f32 "
        "{%0,%1,%2,%3}, {%4,%5,%6,%7}, {%8,%9}, {%0,%1,%2,%3};"
        : "+f"(c[0]), "+f"(c[1]), "+f"(c[2]), "+f"(c[3])
        : "r"(a[0]), "r"(a[1]), "r"(a[2]), "r"(a[3]), "r"(b[0]), "r"(b[1]));
}

// ---------------------------------------------------------------------------
// mma.sync tf32 GEMM v2:  C[M,N] = A[M,K] @ B[K,N]  (both row-major)
// 128x128 tile, BK=32, 256 threads (8 warps, 2x4), warp tile 64x32.
// 3-stage cp.async.cg pipeline, 2 CTAs/SM, tf32 cvt at fragment-load time.
// Fragment indexing / epilogue identical to the verified round-3 kernel.
// ---------------------------------------------------------------------------
static constexpr int A_LD = 36;
static constexpr int B_LD = 136;
static constexpr int A_FLOATS = 128 * A_LD;            // 4608
static constexpr int B_FLOATS = 32 * B_LD;             // 4352
static constexpr int STAGE_FLOATS = A_FLOATS + B_FLOATS;  // 8960
static constexpr int GEMM_STAGES = 3;
static constexpr int GEMM_SMEM_BYTES = GEMM_STAGES * STAGE_FLOATS * 4;  // 107,520

__global__ __launch_bounds__(256, 2) void gemm_mma(
    const float* __restrict__ A, const float* __restrict__ B,
    float* __restrict__ C, int M, int N, int K)
{
    extern __shared__ uint32_t smu[];
    const uint32_t sbase = smem_u32(smu);

    const int tid  = threadIdx.x;
    const int wid  = tid >> 5;
    const int lane = tid & 31;
    const int warpM = wid >> 2;
    const int warpN = wid & 3;
    const int m0 = blockIdx.y * 128;
    const int n0 = blockIdx.x * 128;
    const int r  = lane >> 2;
    const int cq = lane & 3;

    const int arow = tid >> 3;              // + i*32, i=0..3
    const int ac4  = (tid & 7) << 2;
    const int brow = tid >> 5;              // + i*8, i=0..3
    const int bn4  = (tid & 31) << 2;

    float acc[4][4][4];
#pragma unroll
    for (int mi = 0; mi < 4; mi++)
#pragma unroll
        for (int nj = 0; nj < 4; nj++)
#pragma unroll
            for (int t = 0; t < 4; t++) acc[mi][nj][t] = 0.f;

    const int KT = K >> 5;

    // issue all cp.async for K-chunk `it` into stage it%3
    auto issue = [&](int it) {
        const int s = it % GEMM_STAGES;
        const uint32_t as = sbase + (uint32_t)(s * STAGE_FLOATS) * 4u;
        const uint32_t bs = as + (uint32_t)A_FLOATS * 4u;
        const int k0 = it << 5;
#pragma unroll
        for (int i = 0; i < 4; i++) {
            int row = arow + i * 32;
            cp_async16(as + (uint32_t)(row * A_LD + ac4) * 4u,
                       A + (size_t)(m0 + row) * K + k0 + ac4);
        }
#pragma unroll
        for (int i = 0; i < 4; i++) {
            int row = brow + i * 8;
            cp_async16(bs + (uint32_t)(row * B_LD + bn4) * 4u,
                       B + (size_t)(k0 + row) * N + n0 + bn4);
        }
    };

    // prologue: 2 stages in flight
    issue(0); CP_COMMIT();
    issue(1); CP_COMMIT();

    for (int it = 0; it < KT; ++it) {
        CP_WAIT1();            // stage it%3 complete (1 group still pending)
        __syncthreads();

        const uint32_t* as = smu + (it % GEMM_STAGES) * STAGE_FLOATS;
        const uint32_t* bs = as + A_FLOATS;
#pragma unroll
        for (int ks = 0; ks < 4; ++ks) {
            uint32_t af[4][4];
#pragma unroll
            for (int mi = 0; mi < 4; mi++) {
                int rb = (warpM * 64 + mi * 16 + r) * A_LD + ks * 8 + cq;
                af[mi][0] = u2tf32(as[rb]);
                af[mi][1] = u2tf32(as[rb + 8 * A_LD]);
                af[mi][2] = u2tf32(as[rb + 4]);
                af[mi][3] = u2tf32(as[rb + 8 * A_LD + 4]);
            }
            uint32_t bf[4][2];
#pragma unroll
            for (int nj = 0; nj < 4; nj++) {
                int bb = (ks * 8 + cq) * B_LD + warpN * 32 + nj * 8 + r;
                bf[nj][0] = u2tf32(bs[bb]);
                bf[nj][1] = u2tf32(bs[bb + 4 * B_LD]);
            }
#pragma unroll
            for (int mi = 0; mi < 4; mi++)
#pragma unroll
                for (int nj = 0; nj < 4; nj++)
                    mma_tf32(acc[mi][nj], af[mi], bf[nj]);
        }

        // stage (it+2)%3 == (it-1)%3 was fully consumed before the sync above
        if (it + 2 < KT) issue(it + 2);
        CP_COMMIT();           // commit (possibly empty) to keep group count uniform
    }

#pragma unroll
    for (int mi = 0; mi < 4; mi++) {
        const int row0 = m0 + warpM * 64 + mi * 16 + r;
#pragma unroll
        for (int nj = 0; nj < 4; nj++) {
            const int col = n0 + warpN * 32 + nj * 8 + 2 * cq;
            *(float2*)&C[(size_t)row0 * N + col] =
                make_float2(acc[mi][nj][0], acc[mi][nj][1]);
            *(float2*)&C[(size_t)(row0 + 8) * N + col] =
                make_float2(acc[mi][nj][2], acc[mi][nj][3]);
        }
    }
}

// ---------------------------------------------------------------------------
// Tensor-core flash attention (causal), tf32 mma + fp32 online softmax.
// (verified round-7 version, unchanged)
// ---------------------------------------------------------------------------
static constexpr int FQ = 128;
static constexpr int FK = 64;
static constexpr int K_LD = 132;
static constexpr int V_LD = 136;
static constexpr int P_LD = 68;
static constexpr int KW  = 64 * K_LD;
static constexpr int VW  = 64 * V_LD;
static constexpr int PW  = 128 * P_LD;
static constexpr int QFW = 128 * 128;
static constexpr int FLASH_SMEM_BYTES = (KW + VW + PW + QFW) * 4;

__global__ __launch_bounds__(256) void flash_tc(
    const float* __restrict__ Q, const float* __restrict__ K,
    const float* __restrict__ V, float* __restrict__ O)
{
    extern __shared__ uint32_t fsm[];
    uint32_t* Ks = fsm;
    uint32_t* Vs = fsm + KW;
    uint32_t* Ps = fsm + KW + VW;
    uint32_t* Qf = fsm + KW + VW + PW;

    const int tid  = threadIdx.x;
    const int wq   = tid >> 5;
    const int lane = tid & 31;
    const int r    = lane >> 2;
    const int cq   = lane & 3;
    const int mtile = blockIdx.x;
    const int head  = blockIdx.y;
    const int b     = blockIdx.z;
    const int m0    = mtile * FQ;
    const size_t base = ((size_t)b * SEQ) * MODEL + (size_t)head * HDIM;

    for (int it = tid; it < 128 * 32; it += 256) {
        int row = it >> 5, c4 = (it & 31) << 2;
        float4 v = *(const float4*)&Q[base + (size_t)(m0 + row) * MODEL + c4];
        uint4 t = { f2tf32(v.x * SM_SCALE), f2tf32(v.y * SM_SCALE),
                    f2tf32(v.z * SM_SCALE), f2tf32(v.w * SM_SCALE) };
        *(uint4*)&fsm[row * K_LD + c4] = t;
    }
    __syncthreads();

#pragma unroll
    for (int ks = 0; ks < 16; ks++) {
        int rb = (wq * 16 + r) * K_LD + ks * 8 + cq;
        uint4 qv = { fsm[rb], fsm[rb + 8 * K_LD],
                     fsm[rb + 4], fsm[rb + 8 * K_LD + 4] };
        *(uint4*)&Qf[(((wq * 16 + ks) * 32) + lane) * 4] = qv;
    }
    __syncthreads();

    float of[16][4];
#pragma unroll
    for (int nj = 0; nj < 16; nj++)
#pragma unroll
        for (int t = 0; t < 4; t++) of[nj][t] = 0.f;

    float mrow0 = -1e30f, mrow1 = -1e30f, lrow0 = 0.f, lrow1 = 0.f;
    const int row0 = m0 + wq * 16 + r;
    const int row1 = row0 + 8;

    const int NT = 2 * (mtile + 1);
    for (int t = 0; t < NT; t++) {
        const int n0 = t * FK;

        for (int it = tid; it < 64 * 32; it += 256) {
            int row = it >> 5, c4 = (it & 31) << 2;
            size_t g = base + (size_t)(n0 + row) * MODEL + c4;
            float4 k4 = *(const float4*)&K[g];
            float4 v4 = *(const float4*)&V[g];
            uint4 tk = { f2tf32(k4.x), f2tf32(k4.y), f2tf32(k4.z), f2tf32(k4.w) };
            uint4 tv = { f2tf32(v4.x), f2tf32(v4.y), f2tf32(v4.z), f2tf32(v4.w) };
            *(uint4*)&Ks[row * K_LD + c4] = tk;
            *(uint4*)&Vs[row * V_LD + c4] = tv;
        }
        __syncthreads();

        float sc[8][4];
#pragma unroll
        for (int nj = 0; nj < 8; nj++)
#pragma unroll
            for (int e = 0; e < 4; e++) sc[nj][e] = 0.f;

#pragma unroll
        for (int ks = 0; ks < 16; ks++) {
            uint4 qa4 = *(const uint4*)&Qf[(((wq * 16 + ks) * 32) + lane) * 4];
            uint32_t qa[4] = { qa4.x, qa4.y, qa4.z, qa4.w };
            uint32_t bf[8][2];
#pragma unroll
            for (int nj = 0; nj < 8; nj++) {
                int ib = (nj * 8 + r) * K_LD + ks * 8 + cq;
                bf[nj][0] = Ks[ib];
                bf[nj][1] = Ks[ib + 4];
            }
#pragma unroll
            for (int nj = 0; nj < 8; nj++)
                mma_tf32(sc[nj], qa, bf[nj]);
        }

        if (n0 + FK - 1 > m0) {
#pragma unroll
            for (int nj = 0; nj < 8; nj++) {
                int kk = n0 + nj * 8 + 2 * cq;
                if (kk     > row0) sc[nj][0] = -1e30f;
                if (kk + 1 > row0) sc[nj][1] = -1e30f;
                if (kk     > row1) sc[nj][2] = -1e30f;
                if (kk + 1 > row1) sc[nj][3] = -1e30f;
            }
        }

        float tmax0 = -1e30f, tmax1 = -1e30f;
#pragma unroll
        for (int nj = 0; nj < 8; nj++) {
            tmax0 = fmaxf(tmax0, fmaxf(sc[nj][0], sc[nj][1]));
            tmax1 = fmaxf(tmax1, fmaxf(sc[nj][2], sc[nj][3]));
        }
        tmax0 = fmaxf(tmax0, __shfl_xor_sync(0xffffffffu, tmax0, 1));
        tmax0 = fmaxf(tmax0, __shfl_xor_sync(0xffffffffu, tmax0, 2));
        tmax1 = fmaxf(tmax1, __shfl_xor_sync(0xffffffffu, tmax1, 1));
        tmax1 = fmaxf(tmax1, __shfl_xor_sync(0xffffffffu, tmax1, 2));

        float nm0 = fmaxf(mrow0, tmax0);
        float nm1 = fmaxf(mrow1, tmax1);
        float c0 = __expf(mrow0 - nm0);
        float c1 = __expf(mrow1 - nm1);
        float ts0 = 0.f, ts1 = 0.f;
#pragma unroll
        for (int nj = 0; nj < 8; nj++) {
            float p0 = __expf(sc[nj][0] - nm0);
            float p1 = __expf(sc[nj][1] - nm0);
            float p2 = __expf(sc[nj][2] - nm1);
            float p3 = __expf(sc[nj][3] - nm1);
            ts0 += p0 + p1;
            ts1 += p2 + p3;
            uint2 u0 = { f2tf32(p0), f2tf32(p1) };
            uint2 u1 = { f2tf32(p2), f2tf32(p3) };
            *(uint2*)&Ps[(wq * 16 + r) * P_LD + nj * 8 + 2 * cq]     = u0;
            *(uint2*)&Ps[(wq * 16 + r + 8) * P_LD + nj * 8 + 2 * cq] = u1;
        }
        ts0 += __shfl_xor_sync(0xffffffffu, ts0, 1);
        ts0 += __shfl_xor_sync(0xffffffffu, ts0, 2);
        ts1 += __shfl_xor_sync(0xffffffffu, ts1, 1);
        ts1 += __shfl_xor_sync(0xffffffffu, ts1, 2);

        mrow0 = nm0; mrow1 = nm1;
        lrow0 = lrow0 * c0 + ts0;
        lrow1 = lrow1 * c1 + ts1;
#pragma unroll
        for (int nj = 0; nj < 16; nj++) {
            of[nj][0] *= c0; of[nj][1] *= c0;
            of[nj][2] *= c1; of[nj][3] *= c1;
        }
        __syncwarp();

#pragma unroll
        for (int ks = 0; ks < 8; ks++) {
            uint32_t ap[4];
            int rb = (wq * 16 + r) * P_LD + ks * 8 + cq;
            ap[0] = Ps[rb];
            ap[1] = Ps[rb + 8 * P_LD];
            ap[2] = Ps[rb + 4];
            ap[3] = Ps[rb + 8 * P_LD + 4];
            uint32_t bf[16][2];
#pragma unroll
            for (int nj = 0; nj < 16; nj++) {
                int ib = (ks * 8 + cq) * V_LD + nj * 8 + r;
                bf[nj][0] = Vs[ib];
                bf[nj][1] = Vs[ib + 4 * V_LD];
            }
#pragma unroll
            for (int nj = 0; nj < 16; nj++)
                mma_tf32(of[nj], ap, bf[nj]);
        }
        __syncthreads();
    }

    const float inv0 = 1.f / lrow0;
    const float inv1 = 1.f / lrow1;
#pragma unroll
    for (int nj = 0; nj < 16; nj++) {
        int col = nj * 8 + 2 * cq;
        *(float2*)&O[base + (size_t)row0 * MODEL + col] =
            make_float2(of[nj][0] * inv0, of[nj][1] * inv0);
        *(float2*)&O[base + (size_t)row1 * MODEL + col] =
            make_float2(of[nj][2] * inv1, of[nj][3] * inv1);
    }
}

// ---------------------------------------------------------------------------
// Launch
// ---------------------------------------------------------------------------
static inline void run_gemm(const float* A, const float* B, float* C,
                            int M, int N, int K, cudaStream_t stream)
{
    dim3 grid(N / 128, M / 128);
    gemm_mma<<<grid, 256, GEMM_SMEM_BYTES, stream>>>(A, B, C, M, N, K);
}

extern "C" void kernel_launch(void* const* d_in, const int* in_sizes, int n_in,
                              void* d_out, int out_size)
{
    (void)in_sizes; (void)n_in; (void)out_size;
    const float* X     = (const float*)d_in[0];
    const float* w_qa  = (const float*)d_in[1];
    const float* w_qb  = (const float*)d_in[2];
    const float* w_kva = (const float*)d_in[3];
    const float* w_kb  = (const float*)d_in[4];
    const float* w_vb  = (const float*)d_in[5];
    const float* w_o   = (const float*)d_in[6];

    float* attn_out = (float*)d_out;
    float* ckv      = (float*)d_out + (size_t)TOKENS * HID;

    float *qc, *q, *k, *v, *ao;
    cudaGetSymbolAddress((void**)&qc, g_qc);
    cudaGetSymbolAddress((void**)&q,  g_q);
    cudaGetSymbolAddress((void**)&k,  g_k);
    cudaGetSymbolAddress((void**)&v,  g_v);
    cudaGetSymbolAddress((void**)&ao, g_ao);

    cudaFuncSetAttribute(gemm_mma,
                         cudaFuncAttributeMaxDynamicSharedMemorySize,
                         GEMM_SMEM_BYTES);
    cudaFuncSetAttribute(flash_tc,
                         cudaFuncAttributeMaxDynamicSharedMemorySize,
                         FLASH_SMEM_BYTES);

    cudaStream_t stream = 0;

    // projections (tensor-core tf32, cp.async pipeline, 2 CTAs/SM)
    run_gemm(X,   w_qa,  qc,  TOKENS, QRANK,  HID,    stream);
    run_gemm(qc,  w_qb,  q,   TOKENS, MODEL,  QRANK,  stream);
    run_gemm(X,   w_kva, ckv, TOKENS, KVRANK, HID,    stream);
    run_gemm(ckv, w_kb,  k,   TOKENS, MODEL,  KVRANK, stream);
    run_gemm(ckv, w_vb,  v,   TOKENS, MODEL,  KVRANK, stream);

    // causal attention (tensor-core tf32)
    dim3 fgrid(SEQ / FQ, NHEADS, BATCH);
    flash_tc<<<fgrid, 256, FLASH_SMEM_BYTES, stream>>>(q, k, v, ao);

    // output projection
    run_gemm(ao, w_o, attn_out, TOKENS, HID, MODEL, stream);
}

// round 9
// speedup vs baseline: 1.3067x; 1.0700x over previous
#include <cuda_runtime.h>
#include <cuda_bf16.h>
#include <cstdint>
#include <cstddef>

// ---------------------------------------------------------------------------
// Problem constants
// ---------------------------------------------------------------------------
static constexpr int BATCH   = 2;
static constexpr int SEQ     = 2048;
static constexpr int HID     = 4096;
static constexpr int NHEADS  = 32;
static constexpr int HDIM    = 128;
static constexpr int QRANK   = 1536;
static constexpr int KVRANK  = 512;
static constexpr int TOKENS  = BATCH * SEQ;            // 4096
static constexpr int MODEL   = NHEADS * HDIM;          // 4096
static constexpr float SM_SCALE = 0.08838834764831845f; // 1/sqrt(128)

// ---------------------------------------------------------------------------
// Scratch (static device allocations; no cudaMalloc anywhere)
// ---------------------------------------------------------------------------
__device__ float g_qc [(size_t)TOKENS * QRANK];       // tf32 bits
__device__ float g_q  [(size_t)TOKENS * MODEL];       // fp32
__device__ float g_k  [(size_t)TOKENS * MODEL];       // fp32
__device__ float g_v  [(size_t)TOKENS * MODEL];       // fp32
__device__ float g_ao [(size_t)TOKENS * MODEL];       // tf32 bits (flash epilogue cvt)
__device__ float g_xt [(size_t)TOKENS * HID];         // X, tf32 bits
__device__ float g_ckvt[(size_t)TOKENS * KVRANK];     // ckv, tf32 bits
__device__ float g_wqa [(size_t)HID    * QRANK];      // weights, tf32 bits
__device__ float g_wqb [(size_t)QRANK  * MODEL];
__device__ float g_wkva[(size_t)HID    * KVRANK];
__device__ float g_wkb [(size_t)KVRANK * MODEL];
__device__ float g_wvb [(size_t)KVRANK * MODEL];
__device__ float g_wo  [(size_t)MODEL  * HID];

// ---------------------------------------------------------------------------
// Helpers
// ---------------------------------------------------------------------------
__device__ __forceinline__ uint32_t f2tf32(float x) {
    uint32_t r;
    asm("cvt.rna.tf32.f32 %0, %1;" : "=r"(r) : "f"(x));
    return r;
}
__device__ __forceinline__ uint32_t smem_u32(const void* p) {
    uint32_t a;
    asm("{ .reg .u64 t; cvta.to.shared.u64 t, %1; cvt.u32.u64 %0, t; }"
        : "=r"(a) : "l"(p));
    return a;
}
__device__ __forceinline__ void cp_async16(uint32_t s, const void* g) {
    asm volatile("cp.async.cg.shared.global [%0], [%1], 16;" :: "r"(s), "l"(g));
}
#define CP_COMMIT() asm volatile("cp.async.commit_group;" ::: "memory")
#define CP_WAIT1()  asm volatile("cp.async.wait_group 1;" ::: "memory")

__device__ __forceinline__ void mma_tf32(float c[4], const uint32_t a[4],
                                         const uint32_t b[2]) {
    asm volatile(
        "mma.sync.aligned.m16n8k8.row.col.f32.tf32.tf32.f32 "
        "{%0,%1,%2,%3}, {%4,%5,%6,%7}, {%8,%9}, {%0,%1,%2,%3};"
        : "+f"(c[0]), "+f"(c[1]), "+f"(c[2]), "+f"(c[3])
        : "r"(a[0]), "r"(a[1]), "r"(a[2]), "r"(a[3]), "r"(b[0]), "r"(b[1]));
}

// ---------------------------------------------------------------------------
// Elementwise fp32 -> tf32-bit copy (pre-pass, ~45us for all operands)
// ---------------------------------------------------------------------------
__global__ __launch_bounds__(256) void cvt_tf32_kernel(
    const float4* __restrict__ in, uint4* __restrict__ out, int n4)
{
    int i = blockIdx.x * 256 + threadIdx.x;
    if (i < n4) {
        float4 v = in[i];
        out[i] = make_uint4(f2tf32(v.x), f2tf32(v.y), f2tf32(v.z), f2tf32(v.w));
    }
}

// ---------------------------------------------------------------------------
// mma.sync tf32 GEMM v3:  C[M,N] = A[M,K] @ B[K,N]  (row-major)
// A,B hold tf32-bit fp32 (pre-rounded) -> NO cvt in the hot loop.
// 128x128 tile, BK=32, 3-stage cp.async.cg pipeline, 2 CTAs/SM.
// CVT_C: round C to tf32 bits at store. C2 (optional): tf32-bit copy of C.
// ---------------------------------------------------------------------------
static constexpr int A_LD = 36;
static constexpr int B_LD = 136;
static constexpr int A_FLOATS = 128 * A_LD;
static constexpr int B_FLOATS = 32 * B_LD;
static constexpr int STAGE_FLOATS = A_FLOATS + B_FLOATS;
static constexpr int GEMM_STAGES = 3;
static constexpr int GEMM_SMEM_BYTES = GEMM_STAGES * STAGE_FLOATS * 4;  // 107,520

template <bool CVT_C>
__global__ __launch_bounds__(256, 2) void gemm_mma(
    const float* __restrict__ A, const float* __restrict__ B,
    float* __restrict__ C, float* __restrict__ C2, int M, int N, int K)
{
    extern __shared__ uint32_t smu[];
    const uint32_t sbase = smem_u32(smu);

    const int tid  = threadIdx.x;
    const int wid  = tid >> 5;
    const int lane = tid & 31;
    const int warpM = wid >> 2;
    const int warpN = wid & 3;
    const int m0 = blockIdx.y * 128;
    const int n0 = blockIdx.x * 128;
    const int r  = lane >> 2;
    const int cq = lane & 3;

    const int arow = tid >> 3;
    const int ac4  = (tid & 7) << 2;
    const int brow = tid >> 5;
    const int bn4  = (tid & 31) << 2;

    float acc[4][4][4];
#pragma unroll
    for (int mi = 0; mi < 4; mi++)
#pragma unroll
        for (int nj = 0; nj < 4; nj++)
#pragma unroll
            for (int t = 0; t < 4; t++) acc[mi][nj][t] = 0.f;

    const int KT = K >> 5;

    auto issue = [&](int it) {
        const int s = it % GEMM_STAGES;
        const uint32_t as = sbase + (uint32_t)(s * STAGE_FLOATS) * 4u;
        const uint32_t bs = as + (uint32_t)A_FLOATS * 4u;
        const int k0 = it << 5;
#pragma unroll
        for (int i = 0; i < 4; i++) {
            int row = arow + i * 32;
            cp_async16(as + (uint32_t)(row * A_LD + ac4) * 4u,
                       A + (size_t)(m0 + row) * K + k0 + ac4);
        }
#pragma unroll
        for (int i = 0; i < 4; i++) {
            int row = brow + i * 8;
            cp_async16(bs + (uint32_t)(row * B_LD + bn4) * 4u,
                       B + (size_t)(k0 + row) * N + n0 + bn4);
        }
    };

    issue(0); CP_COMMIT();
    issue(1); CP_COMMIT();

    for (int it = 0; it < KT; ++it) {
        CP_WAIT1();
        __syncthreads();

        const uint32_t* as = smu + (it % GEMM_STAGES) * STAGE_FLOATS;
        const uint32_t* bs = as + A_FLOATS;
#pragma unroll
        for (int ks = 0; ks < 4; ++ks) {
            uint32_t af[4][4];
#pragma unroll
            for (int mi = 0; mi < 4; mi++) {
                int rb = (warpM * 64 + mi * 16 + r) * A_LD + ks * 8 + cq;
                af[mi][0] = as[rb];
                af[mi][1] = as[rb + 8 * A_LD];
                af[mi][2] = as[rb + 4];
                af[mi][3] = as[rb + 8 * A_LD + 4];
            }
            uint32_t bf[4][2];
#pragma unroll
            for (int nj = 0; nj < 4; nj++) {
                int bb = (ks * 8 + cq) * B_LD + warpN * 32 + nj * 8 + r;
                bf[nj][0] = bs[bb];
                bf[nj][1] = bs[bb + 4 * B_LD];
            }
#pragma unroll
            for (int mi = 0; mi < 4; mi++)
#pragma unroll
                for (int nj = 0; nj < 4; nj++)
                    mma_tf32(acc[mi][nj], af[mi], bf[nj]);
        }

        if (it + 2 < KT) issue(it + 2);
        CP_COMMIT();
    }

#pragma unroll
    for (int mi = 0; mi < 4; mi++) {
        const int row0 = m0 + warpM * 64 + mi * 16 + r;
#pragma unroll
        for (int nj = 0; nj < 4; nj++) {
            const int col = n0 + warpN * 32 + nj * 8 + 2 * cq;
            size_t o0 = (size_t)row0 * N + col;
            size_t o1 = (size_t)(row0 + 8) * N + col;
            if (CVT_C) {
                *(uint2*)&C[o0] = make_uint2(f2tf32(acc[mi][nj][0]), f2tf32(acc[mi][nj][1]));
                *(uint2*)&C[o1] = make_uint2(f2tf32(acc[mi][nj][2]), f2tf32(acc[mi][nj][3]));
            } else {
                *(float2*)&C[o0] = make_float2(acc[mi][nj][0], acc[mi][nj][1]);
                *(float2*)&C[o1] = make_float2(acc[mi][nj][2], acc[mi][nj][3]);
            }
            if (C2) {
                *(uint2*)&C2[o0] = make_uint2(f2tf32(acc[mi][nj][0]), f2tf32(acc[mi][nj][1]));
                *(uint2*)&C2[o1] = make_uint2(f2tf32(acc[mi][nj][2]), f2tf32(acc[mi][nj][3]));
            }
        }
    }
}

// ---------------------------------------------------------------------------
// Tensor-core flash attention (causal), tf32 mma + fp32 online softmax.
// (verified round-7 version; only the O epilogue now stores tf32 bits so the
// o-projection GEMM can consume it raw.)
// ---------------------------------------------------------------------------
static constexpr int FQ = 128;
static constexpr int FK = 64;
static constexpr int K_LD = 132;
static constexpr int V_LD = 136;
static constexpr int P_LD = 68;
static constexpr int KW  = 64 * K_LD;
static constexpr int VW  = 64 * V_LD;
static constexpr int PW  = 128 * P_LD;
static constexpr int QFW = 128 * 128;
static constexpr int FLASH_SMEM_BYTES = (KW + VW + PW + QFW) * 4;

__global__ __launch_bounds__(256) void flash_tc(
    const float* __restrict__ Q, const float* __restrict__ K,
    const float* __restrict__ V, float* __restrict__ O)
{
    extern __shared__ uint32_t fsm[];
    uint32_t* Ks = fsm;
    uint32_t* Vs = fsm + KW;
    uint32_t* Ps = fsm + KW + VW;
    uint32_t* Qf = fsm + KW + VW + PW;

    const int tid  = threadIdx.x;
    const int wq   = tid >> 5;
    const int lane = tid & 31;
    const int r    = lane >> 2;
    const int cq   = lane & 3;
    const int mtile = blockIdx.x;
    const int head  = blockIdx.y;
    const int b     = blockIdx.z;
    const int m0    = mtile * FQ;
    const size_t base = ((size_t)b * SEQ) * MODEL + (size_t)head * HDIM;

    for (int it = tid; it < 128 * 32; it += 256) {
        int row = it >> 5, c4 = (it & 31) << 2;
        float4 v = *(const float4*)&Q[base + (size_t)(m0 + row) * MODEL + c4];
        uint4 t = { f2tf32(v.x * SM_SCALE), f2tf32(v.y * SM_SCALE),
                    f2tf32(v.z * SM_SCALE), f2tf32(v.w * SM_SCALE) };
        *(uint4*)&fsm[row * K_LD + c4] = t;
    }
    __syncthreads();

#pragma unroll
    for (int ks = 0; ks < 16; ks++) {
        int rb = (wq * 16 + r) * K_LD + ks * 8 + cq;
        uint4 qv = { fsm[rb], fsm[rb + 8 * K_LD],
                     fsm[rb + 4], fsm[rb + 8 * K_LD + 4] };
        *(uint4*)&Qf[(((wq * 16 + ks) * 32) + lane) * 4] = qv;
    }
    __syncthreads();

    float of[16][4];
#pragma unroll
    for (int nj = 0; nj < 16; nj++)
#pragma unroll
        for (int t = 0; t < 4; t++) of[nj][t] = 0.f;

    float mrow0 = -1e30f, mrow1 = -1e30f, lrow0 = 0.f, lrow1 = 0.f;
    const int row0 = m0 + wq * 16 + r;
    const int row1 = row0 + 8;

    const int NT = 2 * (mtile + 1);
    for (int t = 0; t < NT; t++) {
        const int n0 = t * FK;

        for (int it = tid; it < 64 * 32; it += 256) {
            int row = it >> 5, c4 = (it & 31) << 2;
            size_t g = base + (size_t)(n0 + row) * MODEL + c4;
            float4 k4 = *(const float4*)&K[g];
            float4 v4 = *(const float4*)&V[g];
            uint4 tk = { f2tf32(k4.x), f2tf32(k4.y), f2tf32(k4.z), f2tf32(k4.w) };
            uint4 tv = { f2tf32(v4.x), f2tf32(v4.y), f2tf32(v4.z), f2tf32(v4.w) };
            *(uint4*)&Ks[row * K_LD + c4] = tk;
            *(uint4*)&Vs[row * V_LD + c4] = tv;
        }
        __syncthreads();

        float sc[8][4];
#pragma unroll
        for (int nj = 0; nj < 8; nj++)
#pragma unroll
            for (int e = 0; e < 4; e++) sc[nj][e] = 0.f;

#pragma unroll
        for (int ks = 0; ks < 16; ks++) {
            uint4 qa4 = *(const uint4*)&Qf[(((wq * 16 + ks) * 32) + lane) * 4];
            uint32_t qa[4] = { qa4.x, qa4.y, qa4.z, qa4.w };
            uint32_t bf[8][2];
#pragma unroll
            for (int nj = 0; nj < 8; nj++) {
                int ib = (nj * 8 + r) * K_LD + ks * 8 + cq;
                bf[nj][0] = Ks[ib];
                bf[nj][1] = Ks[ib + 4];
            }
#pragma unroll
            for (int nj = 0; nj < 8; nj++)
                mma_tf32(sc[nj], qa, bf[nj]);
        }

        if (n0 + FK - 1 > m0) {
#pragma unroll
            for (int nj = 0; nj < 8; nj++) {
                int kk = n0 + nj * 8 + 2 * cq;
                if (kk     > row0) sc[nj][0] = -1e30f;
                if (kk + 1 > row0) sc[nj][1] = -1e30f;
                if (kk     > row1) sc[nj][2] = -1e30f;
                if (kk + 1 > row1) sc[nj][3] = -1e30f;
            }
        }

        float tmax0 = -1e30f, tmax1 = -1e30f;
#pragma unroll
        for (int nj = 0; nj < 8; nj++) {
            tmax0 = fmaxf(tmax0, fmaxf(sc[nj][0], sc[nj][1]));
            tmax1 = fmaxf(tmax1, fmaxf(sc[nj][2], sc[nj][3]));
        }
        tmax0 = fmaxf(tmax0, __shfl_xor_sync(0xffffffffu, tmax0, 1));
        tmax0 = fmaxf(tmax0, __shfl_xor_sync(0xffffffffu, tmax0, 2));
        tmax1 = fmaxf(tmax1, __shfl_xor_sync(0xffffffffu, tmax1, 1));
        tmax1 = fmaxf(tmax1, __shfl_xor_sync(0xffffffffu, tmax1, 2));

        float nm0 = fmaxf(mrow0, tmax0);
        float nm1 = fmaxf(mrow1, tmax1);
        float c0 = __expf(mrow0 - nm0);
        float c1 = __expf(mrow1 - nm1);
        float ts0 = 0.f, ts1 = 0.f;
#pragma unroll
        for (int nj = 0; nj < 8; nj++) {
            float p0 = __expf(sc[nj][0] - nm0);
            float p1 = __expf(sc[nj][1] - nm0);
            float p2 = __expf(sc[nj][2] - nm1);
            float p3 = __expf(sc[nj][3] - nm1);
            ts0 += p0 + p1;
            ts1 += p2 + p3;
            uint2 u0 = { f2tf32(p0), f2tf32(p1) };
            uint2 u1 = { f2tf32(p2), f2tf32(p3) };
            *(uint2*)&Ps[(wq * 16 + r) * P_LD + nj * 8 + 2 * cq]     = u0;
            *(uint2*)&Ps[(wq * 16 + r + 8) * P_LD + nj * 8 + 2 * cq] = u1;
        }
        ts0 += __shfl_xor_sync(0xffffffffu, ts0, 1);
        ts0 += __shfl_xor_sync(0xffffffffu, ts0, 2);
        ts1 += __shfl_xor_sync(0xffffffffu, ts1, 1);
        ts1 += __shfl_xor_sync(0xffffffffu, ts1, 2);

        mrow0 = nm0; mrow1 = nm1;
        lrow0 = lrow0 * c0 + ts0;
        lrow1 = lrow1 * c1 + ts1;
#pragma unroll
        for (int nj = 0; nj < 16; nj++) {
            of[nj][0] *= c0; of[nj][1] *= c0;
            of[nj][2] *= c1; of[nj][3] *= c1;
        }
        __syncwarp();

#pragma unroll
        for (int ks = 0; ks < 8; ks++) {
            uint32_t ap[4];
            int rb = (wq * 16 + r) * P_LD + ks * 8 + cq;
            ap[0] = Ps[rb];
            ap[1] = Ps[rb + 8 * P_LD];
            ap[2] = Ps[rb + 4];
            ap[3] = Ps[rb + 8 * P_LD + 4];
            uint32_t bf[16][2];
#pragma unroll
            for (int nj = 0; nj < 16; nj++) {
                int ib = (ks * 8 + cq) * V_LD + nj * 8 + r;
                bf[nj][0] = Vs[ib];
                bf[nj][1] = Vs[ib + 4 * V_LD];
            }
#pragma unroll
            for (int nj = 0; nj < 16; nj++)
                mma_tf32(of[nj], ap, bf[nj]);
        }
        __syncthreads();
    }

    // epilogue: store O as tf32 bits (consumed raw by the o-projection GEMM)
    const float inv0 = 1.f / lrow0;
    const float inv1 = 1.f / lrow1;
#pragma unroll
    for (int nj = 0; nj < 16; nj++) {
        int col = nj * 8 + 2 * cq;
        *(uint2*)&O[base + (size_t)row0 * MODEL + col] =
            make_uint2(f2tf32(of[nj][0] * inv0), f2tf32(of[nj][1] * inv0));
        *(uint2*)&O[base + (size_t)row1 * MODEL + col] =
            make_uint2(f2tf32(of[nj][2] * inv1), f2tf32(of[nj][3] * inv1));
    }
}

// ---------------------------------------------------------------------------
// Launch
// ---------------------------------------------------------------------------
template <bool CVT_C>
static inline void run_gemm(const float* A, const float* B, float* C, float* C2,
                            int M, int N, int K, cudaStream_t stream)
{
    dim3 grid(N / 128, M / 128);
    gemm_mma<CVT_C><<<grid, 256, GEMM_SMEM_BYTES, stream>>>(A, B, C, C2, M, N, K);
}

static inline void run_cvt(const float* in, float* out, size_t n, cudaStream_t stream)
{
    int n4 = (int)(n / 4);
    cvt_tf32_kernel<<<(n4 + 255) / 256, 256, 0, stream>>>(
        (const float4*)in, (uint4*)out, n4);
}

extern "C" void kernel_launch(void* const* d_in, const int* in_sizes, int n_in,
                              void* d_out, int out_size)
{
    (void)in_sizes; (void)n_in; (void)out_size;
    const float* X     = (const float*)d_in[0];
    const float* w_qa  = (const float*)d_in[1];
    const float* w_qb  = (const float*)d_in[2];
    const float* w_kva = (const float*)d_in[3];
    const float* w_kb  = (const float*)d_in[4];
    const float* w_vb  = (const float*)d_in[5];
    const float* w_o   = (const float*)d_in[6];

    float* attn_out = (float*)d_out;
    float* ckv      = (float*)d_out + (size_t)TOKENS * HID;

    float *qc, *q, *k, *v, *ao, *xt, *ckvt;
    float *wqa, *wqb, *wkva, *wkb, *wvb, *wo;
    cudaGetSymbolAddress((void**)&qc,   g_qc);
    cudaGetSymbolAddress((void**)&q,    g_q);
    cudaGetSymbolAddress((void**)&k,    g_k);
    cudaGetSymbolAddress((void**)&v,    g_v);
    cudaGetSymbolAddress((void**)&ao,   g_ao);
    cudaGetSymbolAddress((void**)&xt,   g_xt);
    cudaGetSymbolAddress((void**)&ckvt, g_ckvt);
    cudaGetSymbolAddress((void**)&wqa,  g_wqa);
    cudaGetSymbolAddress((void**)&wqb,  g_wqb);
    cudaGetSymbolAddress((void**)&wkva, g_wkva);
    cudaGetSymbolAddress((void**)&wkb,  g_wkb);
    cudaGetSymbolAddress((void**)&wvb,  g_wvb);
    cudaGetSymbolAddress((void**)&wo,   g_wo);

    cudaFuncSetAttribute(gemm_mma<false>,
                         cudaFuncAttributeMaxDynamicSharedMemorySize, GEMM_SMEM_BYTES);
    cudaFuncSetAttribute(gemm_mma<true>,
                         cudaFuncAttributeMaxDynamicSharedMemorySize, GEMM_SMEM_BYTES);
    cudaFuncSetAttribute(flash_tc,
                         cudaFuncAttributeMaxDynamicSharedMemorySize, FLASH_SMEM_BYTES);

    cudaStream_t stream = 0;

    // ---- pre-pass: tf32-round X and all weights (bit-identical math after) ----
    run_cvt(X,     xt,   (size_t)TOKENS * HID,    stream);
    run_cvt(w_qa,  wqa,  (size_t)HID * QRANK,     stream);
    run_cvt(w_qb,  wqb,  (size_t)QRANK * MODEL,   stream);
    run_cvt(w_kva, wkva, (size_t)HID * KVRANK,    stream);
    run_cvt(w_kb,  wkb,  (size_t)KVRANK * MODEL,  stream);
    run_cvt(w_vb,  wvb,  (size_t)KVRANK * MODEL,  stream);
    run_cvt(w_o,   wo,   (size_t)MODEL * HID,     stream);

    // ---- projections (no cvt in GEMM hot loop) ----
    run_gemm<true >(xt,   wqa,  qc,  nullptr, TOKENS, QRANK,  HID,    stream);
    run_gemm<false>(qc,   wqb,  q,   nullptr, TOKENS, MODEL,  QRANK,  stream);
    run_gemm<false>(xt,   wkva, ckv, ckvt,    TOKENS, KVRANK, HID,    stream);
    run_gemm<false>(ckvt, wkb,  k,   nullptr, TOKENS, MODEL,  KVRANK, stream);
    run_gemm<false>(ckvt, wvb,  v,   nullptr, TOKENS, MODEL,  KVRANK, stream);

    // ---- causal attention (tensor-core tf32) ----
    dim3 fgrid(SEQ / FQ, NHEADS, BATCH);
    flash_tc<<<fgrid, 256, FLASH_SMEM_BYTES, stream>>>(q, k, v, ao);

    // ---- output projection (ao already tf32 bits) ----
    run_gemm<false>(ao, wo, attn_out, nullptr, TOKENS, HID, MODEL, stream);
}

// round 10
// speedup vs baseline: 1.3151x; 1.0064x over previous
#include <cuda_runtime.h>
#include <cuda_bf16.h>
#include <cstdint>
#include <cstddef>

// ---------------------------------------------------------------------------
// Problem constants
// ---------------------------------------------------------------------------
static constexpr int BATCH   = 2;
static constexpr int SEQ     = 2048;
static constexpr int HID     = 4096;
static constexpr int NHEADS  = 32;
static constexpr int HDIM    = 128;
static constexpr int QRANK   = 1536;
static constexpr int KVRANK  = 512;
static constexpr int TOKENS  = BATCH * SEQ;            // 4096
static constexpr int MODEL   = NHEADS * HDIM;          // 4096
static constexpr int NQKVA   = QRANK + KVRANK;         // 2048
static constexpr int NKV     = 2 * MODEL;              // 8192
static constexpr float SM_SCALE = 0.08838834764831845f; // 1/sqrt(128)

// ---------------------------------------------------------------------------
// Scratch (static device allocations; no cudaMalloc anywhere)
// ---------------------------------------------------------------------------
__device__ float g_qc  [(size_t)TOKENS * QRANK];       // tf32 bits
__device__ float g_q   [(size_t)TOKENS * MODEL];       // fp32
__device__ float g_kv  [(size_t)TOKENS * NKV];         // fp32: K cols 0-4095, V cols 4096-8191
__device__ float g_ao  [(size_t)TOKENS * MODEL];       // tf32 bits
__device__ float g_xt  [(size_t)TOKENS * HID];         // tf32 bits
__device__ float g_ckvt[(size_t)TOKENS * KVRANK];      // tf32 bits
__device__ float g_wqkva[(size_t)HID   * NQKVA];       // [wqa | wkva], tf32 bits
__device__ float g_wqb [(size_t)QRANK  * MODEL];       // tf32 bits
__device__ float g_wkv8[(size_t)KVRANK * NKV];         // [wkb | wvb], tf32 bits
__device__ float g_wo  [(size_t)MODEL  * HID];         // tf32 bits

// ---------------------------------------------------------------------------
// Helpers
// ---------------------------------------------------------------------------
__device__ __forceinline__ uint32_t f2tf32(float x) {
    uint32_t r;
    asm("cvt.rna.tf32.f32 %0, %1;" : "=r"(r) : "f"(x));
    return r;
}
__device__ __forceinline__ uint32_t smem_u32(const void* p) {
    uint32_t a;
    asm("{ .reg .u64 t; cvta.to.shared.u64 t, %1; cvt.u32.u64 %0, t; }"
        : "=r"(a) : "l"(p));
    return a;
}
__device__ __forceinline__ void cp_async16(uint32_t s, const void* g) {
    asm volatile("cp.async.cg.shared.global [%0], [%1], 16;" :: "r"(s), "l"(g));
}
#define CP_COMMIT() asm volatile("cp.async.commit_group;" ::: "memory")
#define CP_WAIT1()  asm volatile("cp.async.wait_group 1;" ::: "memory")

__device__ __forceinline__ void mma_tf32(float c[4], const uint32_t a[4],
                                         const uint32_t b[2]) {
    asm volatile(
        "mma.sync.aligned.m16n8k8.row.col.f32.tf32.tf32.f32 "
        "{%0,%1,%2,%3}, {%4,%5,%6,%7}, {%8,%9}, {%0,%1,%2,%3};"
        : "+f"(c[0]), "+f"(c[1]), "+f"(c[2]), "+f"(c[3])
        : "r"(a[0]), "r"(a[1]), "r"(a[2]), "r"(a[3]), "r"(b[0]), "r"(b[1]));
}

// ---------------------------------------------------------------------------
// Elementwise fp32 -> tf32-bit copy with output placement:
// in [K, N_in] row-major  ->  out rows with row-stride N_out at column col_off.
// ---------------------------------------------------------------------------
__global__ __launch_bounds__(256) void cvt_tf32_kernel(
    const float4* __restrict__ in, float* __restrict__ out,
    int n4, int nin4, int N_out, int col_off)
{
    int i = blockIdx.x * 256 + threadIdx.x;
    if (i < n4) {
        float4 v = in[i];
        int row = i / nin4;
        int c4  = (i - row * nin4) * 4;
        uint4 t = make_uint4(f2tf32(v.x), f2tf32(v.y), f2tf32(v.z), f2tf32(v.w));
        *(uint4*)&out[(size_t)row * N_out + col_off + c4] = t;
    }
}

// ---------------------------------------------------------------------------
// mma.sync tf32 GEMM:  C[M,N] = A[M,K] @ B[K,N]  (row-major, operands hold
// tf32 bits; no cvt in hot loop). 128x128 tile, BK=32, 3-stage cp.async.
// QKVA epilogue mode: cols < QRANK -> Cq (tf32 bits, stride QRANK);
//                     cols >= QRANK -> Cckv exact + Cckvt tf32 (stride KVRANK).
// ---------------------------------------------------------------------------
static constexpr int A_LD = 36;
static constexpr int B_LD = 136;
static constexpr int A_FLOATS = 128 * A_LD;
static constexpr int B_FLOATS = 32 * B_LD;
static constexpr int STAGE_FLOATS = A_FLOATS + B_FLOATS;
static constexpr int GEMM_STAGES = 3;
static constexpr int GEMM_SMEM_BYTES = GEMM_STAGES * STAGE_FLOATS * 4;  // 107,520

template <bool QKVA>
__global__ __launch_bounds__(256, 2) void gemm_mma(
    const float* __restrict__ A, const float* __restrict__ B,
    float* __restrict__ C, float* __restrict__ Cckv, float* __restrict__ Cckvt,
    int M, int N, int K)
{
    extern __shared__ uint32_t smu[];
    const uint32_t sbase = smem_u32(smu);

    const int tid  = threadIdx.x;
    const int wid  = tid >> 5;
    const int lane = tid & 31;
    const int warpM = wid >> 2;
    const int warpN = wid & 3;
    const int m0 = blockIdx.y * 128;
    const int n0 = blockIdx.x * 128;
    const int r  = lane >> 2;
    const int cq = lane & 3;

    const int arow = tid >> 3;
    const int ac4  = (tid & 7) << 2;
    const int brow = tid >> 5;
    const int bn4  = (tid & 31) << 2;

    float acc[4][4][4];
#pragma unroll
    for (int mi = 0; mi < 4; mi++)
#pragma unroll
        for (int nj = 0; nj < 4; nj++)
#pragma unroll
            for (int t = 0; t < 4; t++) acc[mi][nj][t] = 0.f;

    const int KT = K >> 5;

    auto issue = [&](int it) {
        const int s = it % GEMM_STAGES;
        const uint32_t as = sbase + (uint32_t)(s * STAGE_FLOATS) * 4u;
        const uint32_t bs = as + (uint32_t)A_FLOATS * 4u;
        const int k0 = it << 5;
#pragma unroll
        for (int i = 0; i < 4; i++) {
            int row = arow + i * 32;
            cp_async16(as + (uint32_t)(row * A_LD + ac4) * 4u,
                       A + (size_t)(m0 + row) * K + k0 + ac4);
        }
#pragma unroll
        for (int i = 0; i < 4; i++) {
            int row = brow + i * 8;
            cp_async16(bs + (uint32_t)(row * B_LD + bn4) * 4u,
                       B + (size_t)(k0 + row) * N + n0 + bn4);
        }
    };

    issue(0); CP_COMMIT();
    issue(1); CP_COMMIT();

    for (int it = 0; it < KT; ++it) {
        CP_WAIT1();
        __syncthreads();

        const uint32_t* as = smu + (it % GEMM_STAGES) * STAGE_FLOATS;
        const uint32_t* bs = as + A_FLOATS;
#pragma unroll
        for (int ks = 0; ks < 4; ++ks) {
            uint32_t af[4][4];
#pragma unroll
            for (int mi = 0; mi < 4; mi++) {
                int rb = (warpM * 64 + mi * 16 + r) * A_LD + ks * 8 + cq;
                af[mi][0] = as[rb];
                af[mi][1] = as[rb + 8 * A_LD];
                af[mi][2] = as[rb + 4];
                af[mi][3] = as[rb + 8 * A_LD + 4];
            }
            uint32_t bf[4][2];
#pragma unroll
            for (int nj = 0; nj < 4; nj++) {
                int bb = (ks * 8 + cq) * B_LD + warpN * 32 + nj * 8 + r;
                bf[nj][0] = bs[bb];
                bf[nj][1] = bs[bb + 4 * B_LD];
            }
#pragma unroll
            for (int mi = 0; mi < 4; mi++)
#pragma unroll
                for (int nj = 0; nj < 4; nj++)
                    mma_tf32(acc[mi][nj], af[mi], bf[nj]);
        }

        if (it + 2 < KT) issue(it + 2);
        CP_COMMIT();
    }

#pragma unroll
    for (int mi = 0; mi < 4; mi++) {
        const int row0 = m0 + warpM * 64 + mi * 16 + r;
#pragma unroll
        for (int nj = 0; nj < 4; nj++) {
            const int col = n0 + warpN * 32 + nj * 8 + 2 * cq;
            if (QKVA) {
                if (col < QRANK) {
                    // qc: tf32 bits, row stride QRANK
                    *(uint2*)&C[(size_t)row0 * QRANK + col] =
                        make_uint2(f2tf32(acc[mi][nj][0]), f2tf32(acc[mi][nj][1]));
                    *(uint2*)&C[(size_t)(row0 + 8) * QRANK + col] =
                        make_uint2(f2tf32(acc[mi][nj][2]), f2tf32(acc[mi][nj][3]));
                } else {
                    // ckv: exact fp32 output + tf32 copy, row stride KVRANK
                    int colr = col - QRANK;
                    size_t o0 = (size_t)row0 * KVRANK + colr;
                    size_t o1 = (size_t)(row0 + 8) * KVRANK + colr;
                    *(float2*)&Cckv[o0] = make_float2(acc[mi][nj][0], acc[mi][nj][1]);
                    *(float2*)&Cckv[o1] = make_float2(acc[mi][nj][2], acc[mi][nj][3]);
                    *(uint2*)&Cckvt[o0] =
                        make_uint2(f2tf32(acc[mi][nj][0]), f2tf32(acc[mi][nj][1]));
                    *(uint2*)&Cckvt[o1] =
                        make_uint2(f2tf32(acc[mi][nj][2]), f2tf32(acc[mi][nj][3]));
                }
            } else {
                *(float2*)&C[(size_t)row0 * N + col] =
                    make_float2(acc[mi][nj][0], acc[mi][nj][1]);
                *(float2*)&C[(size_t)(row0 + 8) * N + col] =
                    make_float2(acc[mi][nj][2], acc[mi][nj][3]);
            }
        }
    }
}

// ---------------------------------------------------------------------------
// Tensor-core flash attention (causal), tf32 mma + fp32 online softmax.
// K/V live in one combined buffer KV [tokens, 8192]: K at col head*128,
// V at col 4096 + head*128 (row stride 8192). O epilogue stores tf32 bits.
// ---------------------------------------------------------------------------
static constexpr int FQ = 128;
static constexpr int FK = 64;
static constexpr int K_LD = 132;
static constexpr int V_LD = 136;
static constexpr int P_LD = 68;
static constexpr int KW  = 64 * K_LD;
static constexpr int VW  = 64 * V_LD;
static constexpr int PW  = 128 * P_LD;
static constexpr int QFW = 128 * 128;
static constexpr int FLASH_SMEM_BYTES = (KW + VW + PW + QFW) * 4;

__global__ __launch_bounds__(256) void flash_tc(
    const float* __restrict__ Q, const float* __restrict__ KV,
    float* __restrict__ O)
{
    extern __shared__ uint32_t fsm[];
    uint32_t* Ks = fsm;
    uint32_t* Vs = fsm + KW;
    uint32_t* Ps = fsm + KW + VW;
    uint32_t* Qf = fsm + KW + VW + PW;

    const int tid  = threadIdx.x;
    const int wq   = tid >> 5;
    const int lane = tid & 31;
    const int r    = lane >> 2;
    const int cq   = lane & 3;
    const int mtile = blockIdx.x;
    const int head  = blockIdx.y;
    const int b     = blockIdx.z;
    const int m0    = mtile * FQ;
    const size_t baseQ  = ((size_t)b * SEQ) * MODEL + (size_t)head * HDIM;
    const size_t baseKV = ((size_t)b * SEQ) * NKV   + (size_t)head * HDIM;

    for (int it = tid; it < 128 * 32; it += 256) {
        int row = it >> 5, c4 = (it & 31) << 2;
        float4 v = *(const float4*)&Q[baseQ + (size_t)(m0 + row) * MODEL + c4];
        uint4 t = { f2tf32(v.x * SM_SCALE), f2tf32(v.y * SM_SCALE),
                    f2tf32(v.z * SM_SCALE), f2tf32(v.w * SM_SCALE) };
        *(uint4*)&fsm[row * K_LD + c4] = t;
    }
    __syncthreads();

#pragma unroll
    for (int ks = 0; ks < 16; ks++) {
        int rb = (wq * 16 + r) * K_LD + ks * 8 + cq;
        uint4 qv = { fsm[rb], fsm[rb + 8 * K_LD],
                     fsm[rb + 4], fsm[rb + 8 * K_LD + 4] };
        *(uint4*)&Qf[(((wq * 16 + ks) * 32) + lane) * 4] = qv;
    }
    __syncthreads();

    float of[16][4];
#pragma unroll
    for (int nj = 0; nj < 16; nj++)
#pragma unroll
        for (int t = 0; t < 4; t++) of[nj][t] = 0.f;

    float mrow0 = -1e30f, mrow1 = -1e30f, lrow0 = 0.f, lrow1 = 0.f;
    const int row0 = m0 + wq * 16 + r;
    const int row1 = row0 + 8;

    const int NT = 2 * (mtile + 1);
    for (int t = 0; t < NT; t++) {
        const int n0 = t * FK;

        for (int it = tid; it < 64 * 32; it += 256) {
            int row = it >> 5, c4 = (it & 31) << 2;
            size_t g = baseKV + (size_t)(n0 + row) * NKV + c4;
            float4 k4 = *(const float4*)&KV[g];
            float4 v4 = *(const float4*)&KV[g + MODEL];
            uint4 tk = { f2tf32(k4.x), f2tf32(k4.y), f2tf32(k4.z), f2tf32(k4.w) };
            uint4 tv = { f2tf32(v4.x), f2tf32(v4.y), f2tf32(v4.z), f2tf32(v4.w) };
            *(uint4*)&Ks[row * K_LD + c4] = tk;
            *(uint4*)&Vs[row * V_LD + c4] = tv;
        }
        __syncthreads();

        float sc[8][4];
#pragma unroll
        for (int nj = 0; nj < 8; nj++)
#pragma unroll
            for (int e = 0; e < 4; e++) sc[nj][e] = 0.f;

#pragma unroll
        for (int ks = 0; ks < 16; ks++) {
            uint4 qa4 = *(const uint4*)&Qf[(((wq * 16 + ks) * 32) + lane) * 4];
            uint32_t qa[4] = { qa4.x, qa4.y, qa4.z, qa4.w };
            uint32_t bf[8][2];
#pragma unroll
            for (int nj = 0; nj < 8; nj++) {
                int ib = (nj * 8 + r) * K_LD + ks * 8 + cq;
                bf[nj][0] = Ks[ib];
                bf[nj][1] = Ks[ib + 4];
            }
#pragma unroll
            for (int nj = 0; nj < 8; nj++)
                mma_tf32(sc[nj], qa, bf[nj]);
        }

        if (n0 + FK - 1 > m0) {
#pragma unroll
            for (int nj = 0; nj < 8; nj++) {
                int kk = n0 + nj * 8 + 2 * cq;
                if (kk     > row0) sc[nj][0] = -1e30f;
                if (kk + 1 > row0) sc[nj][1] = -1e30f;
                if (kk     > row1) sc[nj][2] = -1e30f;
                if (kk + 1 > row1) sc[nj][3] = -1e30f;
            }
        }

        float tmax0 = -1e30f, tmax1 = -1e30f;
#pragma unroll
        for (int nj = 0; nj < 8; nj++) {
            tmax0 = fmaxf(tmax0, fmaxf(sc[nj][0], sc[nj][1]));
            tmax1 = fmaxf(tmax1, fmaxf(sc[nj][2], sc[nj][3]));
        }
        tmax0 = fmaxf(tmax0, __shfl_xor_sync(0xffffffffu, tmax0, 1));
        tmax0 = fmaxf(tmax0, __shfl_xor_sync(0xffffffffu, tmax0, 2));
        tmax1 = fmaxf(tmax1, __shfl_xor_sync(0xffffffffu, tmax1, 1));
        tmax1 = fmaxf(tmax1, __shfl_xor_sync(0xffffffffu, tmax1, 2));

        float nm0 = fmaxf(mrow0, tmax0);
        float nm1 = fmaxf(mrow1, tmax1);
        float c0 = __expf(mrow0 - nm0);
        float c1 = __expf(mrow1 - nm1);
        float ts0 = 0.f, ts1 = 0.f;
#pragma unroll
        for (int nj = 0; nj < 8; nj++) {
            float p0 = __expf(sc[nj][0] - nm0);
            float p1 = __expf(sc[nj][1] - nm0);
            float p2 = __expf(sc[nj][2] - nm1);
            float p3 = __expf(sc[nj][3] - nm1);
            ts0 += p0 + p1;
            ts1 += p2 + p3;
            uint2 u0 = { f2tf32(p0), f2tf32(p1) };
            uint2 u1 = { f2tf32(p2), f2tf32(p3) };
            *(uint2*)&Ps[(wq * 16 + r) * P_LD + nj * 8 + 2 * cq]     = u0;
            *(uint2*)&Ps[(wq * 16 + r + 8) * P_LD + nj * 8 + 2 * cq] = u1;
        }
        ts0 += __shfl_xor_sync(0xffffffffu, ts0, 1);
        ts0 += __shfl_xor_sync(0xffffffffu, ts0, 2);
        ts1 += __shfl_xor_sync(0xffffffffu, ts1, 1);
        ts1 += __shfl_xor_sync(0xffffffffu, ts1, 2);

        mrow0 = nm0; mrow1 = nm1;
        lrow0 = lrow0 * c0 + ts0;
        lrow1 = lrow1 * c1 + ts1;
#pragma unroll
        for (int nj = 0; nj < 16; nj++) {
            of[nj][0] *= c0; of[nj][1] *= c0;
            of[nj][2] *= c1; of[nj][3] *= c1;
        }
        __syncwarp();

#pragma unroll
        for (int ks = 0; ks < 8; ks++) {
            uint32_t ap[4];
            int rb = (wq * 16 + r) * P_LD + ks * 8 + cq;
            ap[0] = Ps[rb];
            ap[1] = Ps[rb + 8 * P_LD];
            ap[2] = Ps[rb + 4];
            ap[3] = Ps[rb + 8 * P_LD + 4];
            uint32_t bf[16][2];
#pragma unroll
            for (int nj = 0; nj < 16; nj++) {
                int ib = (ks * 8 + cq) * V_LD + nj * 8 + r;
                bf[nj][0] = Vs[ib];
                bf[nj][1] = Vs[ib + 4 * V_LD];
            }
#pragma unroll
            for (int nj = 0; nj < 16; nj++)
                mma_tf32(of[nj], ap, bf[nj]);
        }
        __syncthreads();
    }

    const float inv0 = 1.f / lrow0;
    const float inv1 = 1.f / lrow1;
#pragma unroll
    for (int nj = 0; nj < 16; nj++) {
        int col = nj * 8 + 2 * cq;
        *(uint2*)&O[baseQ + (size_t)row0 * MODEL + col] =
            make_uint2(f2tf32(of[nj][0] * inv0), f2tf32(of[nj][1] * inv0));
        *(uint2*)&O[baseQ + (size_t)row1 * MODEL + col] =
            make_uint2(f2tf32(of[nj][2] * inv1), f2tf32(of[nj][3] * inv1));
    }
}

// ---------------------------------------------------------------------------
// Launch
// ---------------------------------------------------------------------------
static inline void run_cvt(const float* in, float* out, int K, int N_in,
                           int N_out, int col_off, cudaStream_t stream)
{
    int n4 = K * (N_in / 4);
    cvt_tf32_kernel<<<(n4 + 255) / 256, 256, 0, stream>>>(
        (const float4*)in, out, n4, N_in / 4, N_out, col_off);
}

extern "C" void kernel_launch(void* const* d_in, const int* in_sizes, int n_in,
                              void* d_out, int out_size)
{
    (void)in_sizes; (void)n_in; (void)out_size;
    const float* X     = (const float*)d_in[0];
    const float* w_qa  = (const float*)d_in[1];
    const float* w_qb  = (const float*)d_in[2];
    const float* w_kva = (const float*)d_in[3];
    const float* w_kb  = (const float*)d_in[4];
    const float* w_vb  = (const float*)d_in[5];
    const float* w_o   = (const float*)d_in[6];

    float* attn_out = (float*)d_out;
    float* ckv      = (float*)d_out + (size_t)TOKENS * HID;

    float *qc, *q, *kv, *ao, *xt, *ckvt, *wqkva, *wqb, *wkv8, *wo;
    cudaGetSymbolAddress((void**)&qc,    g_qc);
    cudaGetSymbolAddress((void**)&q,     g_q);
    cudaGetSymbolAddress((void**)&kv,    g_kv);
    cudaGetSymbolAddress((void**)&ao,    g_ao);
    cudaGetSymbolAddress((void**)&xt,    g_xt);
    cudaGetSymbolAddress((void**)&ckvt,  g_ckvt);
    cudaGetSymbolAddress((void**)&wqkva, g_wqkva);
    cudaGetSymbolAddress((void**)&wqb,   g_wqb);
    cudaGetSymbolAddress((void**)&wkv8,  g_wkv8);
    cudaGetSymbolAddress((void**)&wo,    g_wo);

    cudaFuncSetAttribute(gemm_mma<false>,
                         cudaFuncAttributeMaxDynamicSharedMemorySize, GEMM_SMEM_BYTES);
    cudaFuncSetAttribute(gemm_mma<true>,
                         cudaFuncAttributeMaxDynamicSharedMemorySize, GEMM_SMEM_BYTES);
    cudaFuncSetAttribute(flash_tc,
                         cudaFuncAttributeMaxDynamicSharedMemorySize, FLASH_SMEM_BYTES);

    cudaStream_t stream = 0;

    // ---- pre-pass: tf32-round inputs; concatenate fused weight buffers ----
    run_cvt(X,     xt,    TOKENS, HID,    HID,   0,      stream);
    run_cvt(w_qa,  wqkva, HID,    QRANK,  NQKVA, 0,      stream);
    run_cvt(w_kva, wqkva, HID,    KVRANK, NQKVA, QRANK,  stream);
    run_cvt(w_qb,  wqb,   QRANK,  MODEL,  MODEL, 0,      stream);
    run_cvt(w_kb,  wkv8,  KVRANK, MODEL,  NKV,   0,      stream);
    run_cvt(w_vb,  wkv8,  KVRANK, MODEL,  NKV,   MODEL,  stream);
    run_cvt(w_o,   wo,    MODEL,  HID,    HID,   0,      stream);

    // ---- fused qc+ckv projection: xt @ [wqa | wkva] ----
    {
        dim3 grid(NQKVA / 128, TOKENS / 128);
        gemm_mma<true><<<grid, 256, GEMM_SMEM_BYTES, stream>>>(
            xt, wqkva, qc, ckv, ckvt, TOKENS, NQKVA, HID);
    }
    // ---- q projection ----
    {
        dim3 grid(MODEL / 128, TOKENS / 128);
        gemm_mma<false><<<grid, 256, GEMM_SMEM_BYTES, stream>>>(
            qc, wqb, q, nullptr, nullptr, TOKENS, MODEL, QRANK);
    }
    // ---- fused k+v projection: ckvt @ [wkb | wvb] -> kv [tokens, 8192] ----
    {
        dim3 grid(NKV / 128, TOKENS / 128);
        gemm_mma<false><<<grid, 256, GEMM_SMEM_BYTES, stream>>>(
            ckvt, wkv8, kv, nullptr, nullptr, TOKENS, NKV, KVRANK);
    }

    // ---- causal attention ----
    dim3 fgrid(SEQ / FQ, NHEADS, BATCH);
    flash_tc<<<fgrid, 256, FLASH_SMEM_BYTES, stream>>>(q, kv, ao);

    // ---- output projection ----
    {
        dim3 grid(HID / 128, TOKENS / 128);
        gemm_mma<false><<<grid, 256, GEMM_SMEM_BYTES, stream>>>(
            ao, wo, attn_out, nullptr, nullptr, TOKENS, HID, MODEL);
    }
}